// round 1
// baseline (speedup 1.0000x reference)
#include <cuda_runtime.h>
#include <cuda_bf16.h>
#include <math.h>

// Problem constants
#define NN 8192      // nodes
#define NE 2048      // edges
#define LL 8         // tokens per node/edge
#define DD 64        // gnn hidden
#define FD 512       // LL*DD
#define DG 256       // gpt hidden
#define VV 10000     // vocab
#define NTOK 16384   // NE*LL

// ---------------- device scratch (static, allocation-free) ----------------
__device__ float g_x[NN * FD];
__device__ float g_e[NE * FD];
__device__ float g_msg[NE * FD];
__device__ float g_agg[NN * FD];
__device__ float g_h[NN * FD];
__device__ float g_z[NTOK * DG];
__device__ float g_q[NTOK * DG];
__device__ float g_k[NTOK * DG];
__device__ float g_v[NTOK * DG];
__device__ float g_attn[NTOK * DG];
__device__ float g_x1[NTOK * DG];
__device__ float g_ffn[NTOK * 4 * DG];
__device__ float g_x2[NTOK * DG];
__device__ float g_y[NTOK * DD];
__device__ float g_logits[(size_t)NTOK * VV];   // 655 MB

// ---------------- small kernels ----------------

__global__ void zero_kernel(float* __restrict__ p, int n) {
    int i = blockIdx.x * blockDim.x + threadIdx.x;
    if (i < n) p[i] = 0.0f;
}

// node embedding gather: x[n, l*64+d] = emb[node_tokens[n,l], d]
__global__ void node_embed_kernel(const int* __restrict__ ntok,
                                  const float* __restrict__ emb,
                                  float* __restrict__ x) {
    int i = blockIdx.x * blockDim.x + threadIdx.x;
    if (i < NN * FD) {
        int row = i >> 9;        // /512
        int col = i & 511;
        int l = col >> 6, d = col & 63;
        x[i] = emb[(size_t)ntok[row * LL + l] * DD + d];
    }
}

// per-edge masking + label + masked embedding gather
__global__ void edge_mask_embed_kernel(const int* __restrict__ etok,
                                       const int* __restrict__ mask_rows,
                                       const float* __restrict__ emb,
                                       float* __restrict__ e_out,
                                       float* __restrict__ labels_out) {
    int b = blockIdx.x;  // edge
    __shared__ int mt[LL];
    int t = threadIdx.x;
    if (t < LL) {
        int tok = etok[b * LL + t];
        bool special = ((unsigned)tok) < 4u;              // tokens {0,1,2,3}
        bool masked = (mask_rows[b] != 0) && !special;    // nonzero works for i32 or f32 bits
        mt[t] = masked ? 4 : tok;                         // MASK_ID = 4
        if (labels_out) labels_out[b * LL + t] = masked ? (float)tok : -100.0f;
    }
    __syncthreads();
    for (int c = t; c < FD; c += blockDim.x) {
        int l = c >> 6, d = c & 63;
        e_out[(size_t)b * FD + c] = emb[(size_t)mt[l] * DD + d];
    }
}

// scatter-add: agg[dst[e], :] += msg[e, :]
__global__ void scatter_add_kernel(const float* __restrict__ msg,
                                   const int* __restrict__ dst,
                                   float* __restrict__ agg) {
    int i = blockIdx.x * blockDim.x + threadIdx.x;
    if (i < NE * FD) {
        int e = i >> 9;
        int n = i & 511;
        atomicAdd(&agg[(size_t)dst[e] * FD + n], msg[i]);
    }
}

// ---------------- generic tiled SGEMM ----------------
// C[M,N] = epi(A[M,K] @ B[K,N])
// AMODE 0: A row-major. AMODE 1: A row m = h[src[e]*512 + l*64 + k] + h[dst[e]*...], m=(e<<3)|l, K=64.
// BMODE 0: B row-major [K,N]. BMODE 1: B stored [N,K] (i.e. B_logical[k,n] = Bptr[n*K+k]).
// EPI: 0 none, 1 +bias[n], 2 relu(.+extra[m,n]), 3 relu(.+extra[idxa[m],n]), 4 .+extra[m,n], 5 gelu(tanh approx)
#define BM 64
#define BN 64
#define BK 32

template <int AMODE, int BMODE, int EPI>
__global__ __launch_bounds__(256)
void gemm_kernel(const float* __restrict__ A, const float* __restrict__ B,
                 float* __restrict__ C, int M, int N, int K,
                 const float* __restrict__ bias, const float* __restrict__ extra,
                 const int* __restrict__ idxa, const int* __restrict__ idxb) {
    __shared__ float As[BK][BM];
    __shared__ float Bs[BK][BN];

    int tid = threadIdx.x;
    int tx = tid & 15;       // 0..15 -> 4 cols each
    int ty = tid >> 4;       // 0..15 -> 4 rows each
    int m0 = blockIdx.y * BM;
    int n0 = blockIdx.x * BN;

    float acc[4][4] = {};

    for (int k0 = 0; k0 < K; k0 += BK) {
        // ---- load A tile (64x32) : 512 float4 slots, 2 per thread ----
        #pragma unroll
        for (int it = 0; it < 2; it++) {
            int s = tid + it * 256;
            int m = s >> 3;
            int k4 = (s & 7) * 4;
            float4 av;
            if (AMODE == 0) {
                av = *(const float4*)(A + (size_t)(m0 + m) * K + k0 + k4);
            } else {
                int mg = m0 + m;
                int e = mg >> 3, l = mg & 7;
                const float4 u = *(const float4*)(A + (size_t)idxa[e] * FD + l * DD + k0 + k4);
                const float4 w = *(const float4*)(A + (size_t)idxb[e] * FD + l * DD + k0 + k4);
                av = make_float4(u.x + w.x, u.y + w.y, u.z + w.z, u.w + w.w);
            }
            As[k4 + 0][m] = av.x;
            As[k4 + 1][m] = av.y;
            As[k4 + 2][m] = av.z;
            As[k4 + 3][m] = av.w;
        }
        // ---- load B tile (32x64) ----
        #pragma unroll
        for (int it = 0; it < 2; it++) {
            int s = tid + it * 256;
            if (BMODE == 0) {
                int k = s >> 4;
                int n4 = (s & 15) * 4;
                float4 bv = make_float4(0.f, 0.f, 0.f, 0.f);
                if (n0 + n4 < N)
                    bv = *(const float4*)(B + (size_t)(k0 + k) * N + n0 + n4);
                *(float4*)&Bs[k][n4] = bv;
            } else {
                int n = s >> 3;
                int k4 = (s & 7) * 4;
                float4 bv = make_float4(0.f, 0.f, 0.f, 0.f);
                if (n0 + n < N)
                    bv = *(const float4*)(B + (size_t)(n0 + n) * K + k0 + k4);
                Bs[k4 + 0][n] = bv.x;
                Bs[k4 + 1][n] = bv.y;
                Bs[k4 + 2][n] = bv.z;
                Bs[k4 + 3][n] = bv.w;
            }
        }
        __syncthreads();

        #pragma unroll
        for (int kk = 0; kk < BK; kk++) {
            float4 a4 = *(const float4*)&As[kk][ty * 4];
            float4 b4 = *(const float4*)&Bs[kk][tx * 4];
            float av[4] = {a4.x, a4.y, a4.z, a4.w};
            float bv[4] = {b4.x, b4.y, b4.z, b4.w};
            #pragma unroll
            for (int i = 0; i < 4; i++)
                #pragma unroll
                for (int j = 0; j < 4; j++)
                    acc[i][j] = fmaf(av[i], bv[j], acc[i][j]);
        }
        __syncthreads();
    }

    // ---- epilogue ----
    #pragma unroll
    for (int i = 0; i < 4; i++) {
        int m = m0 + ty * 4 + i;
        #pragma unroll
        for (int j = 0; j < 4; j++) {
            int n = n0 + tx * 4 + j;
            if (n < N) {
                float v = acc[i][j];
                if (EPI == 1) v += bias[n];
                else if (EPI == 2) { v += extra[(size_t)m * N + n]; v = fmaxf(v, 0.0f); }
                else if (EPI == 3) { v += extra[(size_t)idxa[m] * N + n]; v = fmaxf(v, 0.0f); }
                else if (EPI == 4) { v += extra[(size_t)m * N + n]; }
                else if (EPI == 5) {
                    float c = v + 0.044715f * v * v * v;
                    v = 0.5f * v * (1.0f + tanhf(0.7978845608028654f * c));
                }
                C[(size_t)m * N + n] = v;
            }
        }
    }
}

// ---------------- per-(edge,head) attention: one warp each ----------------
__global__ void attn_kernel(const float* __restrict__ q, const float* __restrict__ k,
                            const float* __restrict__ v, float* __restrict__ o) {
    int b = blockIdx.x;              // edge 0..2047
    int h = threadIdx.x >> 5;        // 0..3
    int lane = threadIdx.x & 31;
    int d0 = lane * 2;

    const size_t base = (size_t)b * LL * DG + h * 64 + d0;
    float qr[LL][2], kr[LL][2], vr[LL][2];
    #pragma unroll
    for (int i = 0; i < LL; i++) {
        qr[i][0] = q[base + (size_t)i * DG];     qr[i][1] = q[base + (size_t)i * DG + 1];
        kr[i][0] = k[base + (size_t)i * DG];     kr[i][1] = k[base + (size_t)i * DG + 1];
        vr[i][0] = v[base + (size_t)i * DG];     vr[i][1] = v[base + (size_t)i * DG + 1];
    }

    float att[LL][LL];
    #pragma unroll
    for (int i = 0; i < LL; i++)
        #pragma unroll
        for (int j = 0; j < LL; j++) {
            float p = qr[i][0] * kr[j][0] + qr[i][1] * kr[j][1];
            #pragma unroll
            for (int off = 16; off > 0; off >>= 1)
                p += __shfl_xor_sync(0xffffffffu, p, off);
            att[i][j] = p * 0.125f;   // 1/sqrt(64)
        }

    #pragma unroll
    for (int i = 0; i < LL; i++) {
        float mx = att[i][0];
        #pragma unroll
        for (int j = 1; j < LL; j++) mx = fmaxf(mx, att[i][j]);
        float s = 0.0f;
        #pragma unroll
        for (int j = 0; j < LL; j++) { att[i][j] = expf(att[i][j] - mx); s += att[i][j]; }
        float inv = 1.0f / s;
        float o0 = 0.0f, o1 = 0.0f;
        #pragma unroll
        for (int j = 0; j < LL; j++) {
            float a = att[i][j] * inv;
            o0 = fmaf(a, vr[j][0], o0);
            o1 = fmaf(a, vr[j][1], o1);
        }
        o[base + (size_t)i * DG] = o0;
        o[base + (size_t)i * DG + 1] = o1;
    }
}

// ---------------- final softmax over V per row ----------------
__global__ __launch_bounds__(256)
void lm_softmax_kernel(const float* __restrict__ logits, float* __restrict__ probs) {
    int r = blockIdx.x;   // 0..16383
    int t = threadIdx.x;  // 256
    const float* row = logits + (size_t)r * VV;
    float* orow = probs + (size_t)r * VV;

    float vals[40];
    float mx = -INFINITY;
    #pragma unroll
    for (int i = 0; i < 40; i++) {
        int c = t + i * 256;
        vals[i] = (c < VV) ? row[c] : -INFINITY;
        mx = fmaxf(mx, vals[i]);
    }
    __shared__ float sred[8];
    // block max
    #pragma unroll
    for (int off = 16; off > 0; off >>= 1) mx = fmaxf(mx, __shfl_xor_sync(0xffffffffu, mx, off));
    if ((t & 31) == 0) sred[t >> 5] = mx;
    __syncthreads();
    if (t < 32) {
        float v2 = (t < 8) ? sred[t] : -INFINITY;
        #pragma unroll
        for (int off = 4; off > 0; off >>= 1) v2 = fmaxf(v2, __shfl_xor_sync(0xffffffffu, v2, off));
        if (t == 0) sred[0] = v2;
    }
    __syncthreads();
    mx = sred[0];
    __syncthreads();

    float s = 0.0f;
    #pragma unroll
    for (int i = 0; i < 40; i++) {
        int c = t + i * 256;
        if (c < VV) { vals[i] = expf(vals[i] - mx); s += vals[i]; }
    }
    // block sum
    #pragma unroll
    for (int off = 16; off > 0; off >>= 1) s += __shfl_xor_sync(0xffffffffu, s, off);
    if ((t & 31) == 0) sred[t >> 5] = s;
    __syncthreads();
    if (t < 32) {
        float v2 = (t < 8) ? sred[t] : 0.0f;
        #pragma unroll
        for (int off = 4; off > 0; off >>= 1) v2 += __shfl_xor_sync(0xffffffffu, v2, off);
        if (t == 0) sred[0] = v2;
    }
    __syncthreads();
    float inv = 1.0f / sred[0];

    #pragma unroll
    for (int i = 0; i < 40; i++) {
        int c = t + i * 256;
        if (c < VV) orow[c] = vals[i] * inv;
    }
}

// ---------------- host launch ----------------
extern "C" void kernel_launch(void* const* d_in, const int* in_sizes, int n_in,
                              void* d_out, int out_size) {
    const int* node_tokens = (const int*)d_in[0];
    const int* edge_tokens = (const int*)d_in[1];
    const int* edge_index  = (const int*)d_in[2];
    const int* mask_rows   = (const int*)d_in[3];
    const float* emb    = (const float*)d_in[4];
    const float* W_msg  = (const float*)d_in[5];
    const float* W_node = (const float*)d_in[6];
    const float* lc1_w  = (const float*)d_in[7];
    const float* lc1_b  = (const float*)d_in[8];
    const float* lc2_w  = (const float*)d_in[9];
    const float* lc2_b  = (const float*)d_in[10];
    const float* Wq  = (const float*)d_in[11];
    const float* Wk  = (const float*)d_in[12];
    const float* Wv  = (const float*)d_in[13];
    const float* Wo  = (const float*)d_in[14];
    const float* Wf1 = (const float*)d_in[15];
    const float* Wf2 = (const float*)d_in[16];

    const int* src = edge_index;        // edge_index[0, :]
    const int* dst = edge_index + NE;   // edge_index[1, :]

    float* out = (float*)d_out;
    float* labels_ptr = nullptr;
    float* probs_ptr  = nullptr;
    long total = (long)NTOK * VV;       // 163,840,000
    if ((long)out_size >= total + NTOK) { labels_ptr = out; probs_ptr = out + NTOK; }
    else if ((long)out_size >= total)   { probs_ptr = out; }
    else                                { labels_ptr = out; }

    // scratch pointers
    void *px, *pe, *pmsg, *pagg, *ph, *pz, *pq, *pk, *pv, *pattn, *px1, *pffn, *px2, *py, *plog;
    cudaGetSymbolAddress(&px, g_x);      cudaGetSymbolAddress(&pe, g_e);
    cudaGetSymbolAddress(&pmsg, g_msg);  cudaGetSymbolAddress(&pagg, g_agg);
    cudaGetSymbolAddress(&ph, g_h);      cudaGetSymbolAddress(&pz, g_z);
    cudaGetSymbolAddress(&pq, g_q);      cudaGetSymbolAddress(&pk, g_k);
    cudaGetSymbolAddress(&pv, g_v);      cudaGetSymbolAddress(&pattn, g_attn);
    cudaGetSymbolAddress(&px1, g_x1);    cudaGetSymbolAddress(&pffn, g_ffn);
    cudaGetSymbolAddress(&px2, g_x2);    cudaGetSymbolAddress(&py, g_y);
    cudaGetSymbolAddress(&plog, g_logits);
    float *X = (float*)px, *E = (float*)pe, *MSG = (float*)pmsg, *AGG = (float*)pagg;
    float *H = (float*)ph, *Z = (float*)pz, *Q = (float*)pq, *Kb = (float*)pk, *Vb = (float*)pv;
    float *AT = (float*)pattn, *X1 = (float*)px1, *FFN = (float*)pffn, *X2 = (float*)px2;
    float *Y = (float*)py, *LOG = (float*)plog;

    // 1. embeddings
    node_embed_kernel<<<(NN * FD + 255) / 256, 256>>>(node_tokens, emb, X);
    edge_mask_embed_kernel<<<NE, 256>>>(edge_tokens, mask_rows, emb, E, labels_ptr);

    if (probs_ptr == nullptr) return;   // labels-only layout: done

    // 2. msg = relu(e @ W_msg + x[src])
    gemm_kernel<0, 0, 3><<<dim3(FD / BN, NE / BM), 256>>>(E, W_msg, MSG, NE, FD, FD,
                                                          nullptr, X, src, nullptr);
    // 3. agg = segment_sum(msg, dst)
    zero_kernel<<<(NN * FD + 255) / 256, 256>>>(AGG, NN * FD);
    scatter_add_kernel<<<(NE * FD + 255) / 256, 256>>>(MSG, dst, AGG);
    // 4. h = relu(x @ W_node + agg)
    gemm_kernel<0, 0, 2><<<dim3(FD / BN, NN / BM), 256>>>(X, W_node, H, NN, FD, FD,
                                                          nullptr, AGG, nullptr, nullptr);
    // 5. z = (h[src]+h[dst]).reshape(.,L,D) @ lc1_w + lc1_b
    gemm_kernel<1, 0, 1><<<dim3(DG / BN, NTOK / BM), 256>>>(H, lc1_w, Z, NTOK, DG, DD,
                                                            lc1_b, nullptr, src, dst);
    // 6. q, k, v
    gemm_kernel<0, 0, 0><<<dim3(DG / BN, NTOK / BM), 256>>>(Z, Wq, Q, NTOK, DG, DG,
                                                            nullptr, nullptr, nullptr, nullptr);
    gemm_kernel<0, 0, 0><<<dim3(DG / BN, NTOK / BM), 256>>>(Z, Wk, Kb, NTOK, DG, DG,
                                                            nullptr, nullptr, nullptr, nullptr);
    gemm_kernel<0, 0, 0><<<dim3(DG / BN, NTOK / BM), 256>>>(Z, Wv, Vb, NTOK, DG, DG,
                                                            nullptr, nullptr, nullptr, nullptr);
    // 7. attention
    attn_kernel<<<NE, 128>>>(Q, Kb, Vb, AT);
    // 8. x1 = z + attn @ Wo
    gemm_kernel<0, 0, 4><<<dim3(DG / BN, NTOK / BM), 256>>>(AT, Wo, X1, NTOK, DG, DG,
                                                            nullptr, Z, nullptr, nullptr);
    // 9. ffn = gelu(x1 @ Wf1)
    gemm_kernel<0, 0, 5><<<dim3(4 * DG / BN, NTOK / BM), 256>>>(X1, Wf1, FFN, NTOK, 4 * DG, DG,
                                                                nullptr, nullptr, nullptr, nullptr);
    // 10. x2 = x1 + ffn @ Wf2
    gemm_kernel<0, 0, 4><<<dim3(DG / BN, NTOK / BM), 256>>>(FFN, Wf2, X2, NTOK, DG, 4 * DG,
                                                            nullptr, X1, nullptr, nullptr);
    // 11. y = x2 @ lc2_w + lc2_b
    gemm_kernel<0, 0, 1><<<dim3(1, NTOK / BM), 256>>>(X2, lc2_w, Y, NTOK, DD, DG,
                                                      lc2_b, nullptr, nullptr, nullptr);
    // 12. logits = y @ emb.T   (B stored [V, D] -> BMODE 1)
    gemm_kernel<0, 1, 0><<<dim3((VV + BN - 1) / BN, NTOK / BM), 256>>>(Y, emb, LOG, NTOK, VV, DD,
                                                                       nullptr, nullptr, nullptr, nullptr);
    // 13. probs = softmax(logits)
    lm_softmax_kernel<<<NTOK, 256>>>(LOG, probs_ptr);
}

// round 4
// speedup vs baseline: 1.4262x; 1.4262x over previous
#include <cuda_runtime.h>
#include <cuda_bf16.h>
#include <math.h>

// Problem constants
#define NN 8192      // nodes
#define NE 2048      // edges
#define LL 8         // tokens per node/edge
#define DD 64        // gnn hidden
#define FD 512       // LL*DD
#define DG 256       // gpt hidden
#define VV 10000     // vocab
#define NTOK 16384   // NE*LL

// ---------------- device scratch (static, allocation-free) ----------------
__device__ float g_x[NN * FD];
__device__ float g_e[NE * FD];
__device__ float g_msg[NE * FD];
__device__ float g_agg[NN * FD];
__device__ float g_h[NN * FD];
__device__ float g_z[NTOK * DG];
__device__ float g_q[NTOK * DG];
__device__ float g_k[NTOK * DG];
__device__ float g_v[NTOK * DG];
__device__ float g_attn[NTOK * DG];
__device__ float g_x1[NTOK * DG];
__device__ float g_ffn[NTOK * 4 * DG];
__device__ float g_x2[NTOK * DG];
__device__ float g_y[NTOK * DD];
__device__ float g_logits[(size_t)NTOK * VV];   // 655 MB

// ---------------- f32x2 packed math helpers ----------------
typedef unsigned long long ull;

__device__ __forceinline__ ull pack2(float lo, float hi) {
    ull r; asm("mov.b64 %0, {%1, %2};" : "=l"(r) : "f"(lo), "f"(hi)); return r;
}
__device__ __forceinline__ void unpack2(ull v, float& lo, float& hi) {
    asm("mov.b64 {%0, %1}, %2;" : "=f"(lo), "=f"(hi) : "l"(v));
}
__device__ __forceinline__ ull fma2(ull a, ull b, ull c) {
    ull d; asm("fma.rn.f32x2 %0, %1, %2, %3;" : "=l"(d) : "l"(a), "l"(b), "l"(c)); return d;
}

// ---------------- small kernels ----------------

__global__ void zero_kernel(float* __restrict__ p, int n) {
    int i = blockIdx.x * blockDim.x + threadIdx.x;
    if (i < n) p[i] = 0.0f;
}

__global__ void node_embed_kernel(const int* __restrict__ ntok,
                                  const float* __restrict__ emb,
                                  float* __restrict__ x) {
    int i = blockIdx.x * blockDim.x + threadIdx.x;
    if (i < NN * FD) {
        int row = i >> 9;
        int col = i & 511;
        int l = col >> 6, d = col & 63;
        x[i] = emb[(size_t)ntok[row * LL + l] * DD + d];
    }
}

__global__ void edge_mask_embed_kernel(const int* __restrict__ etok,
                                       const int* __restrict__ mask_rows,
                                       const float* __restrict__ emb,
                                       float* __restrict__ e_out,
                                       float* __restrict__ labels_out) {
    int b = blockIdx.x;
    __shared__ int mt[LL];
    int t = threadIdx.x;
    if (t < LL) {
        int tok = etok[b * LL + t];
        bool special = ((unsigned)tok) < 4u;
        bool masked = (mask_rows[b] != 0) && !special;
        mt[t] = masked ? 4 : tok;
        if (labels_out) labels_out[b * LL + t] = masked ? (float)tok : -100.0f;
    }
    __syncthreads();
    for (int c = t; c < FD; c += blockDim.x) {
        int l = c >> 6, d = c & 63;
        e_out[(size_t)b * FD + c] = emb[(size_t)mt[l] * DD + d];
    }
}

__global__ void scatter_add_kernel(const float* __restrict__ msg,
                                   const int* __restrict__ dst,
                                   float* __restrict__ agg) {
    int i = blockIdx.x * blockDim.x + threadIdx.x;
    if (i < NE * FD) {
        int e = i >> 9;
        int n = i & 511;
        atomicAdd(&agg[(size_t)dst[e] * FD + n], msg[i]);
    }
}

// ---------------- 128x128x16 f32x2 SGEMM ----------------
// C[M,N] = epi(A[M,K] @ B[K,N])
// AMODE 0: A row-major [M,K]. AMODE 1: A row m = h[src[e]]+h[dst[e]] slice, m=(e<<3)|l, K=64.
// BMODE 0: B row-major [K,N]. BMODE 1: B stored [N,K].
// EPI: 0 none, 1 +bias[n], 2 relu(.+extra[m,n]), 3 relu(.+extra[idxa[m],n]),
//      4 .+extra[m,n], 5 gelu(tanh approx)
// Requirements: M % 128 == 0, K % 16 == 0, N % 16 == 0 (guards on N tile edge).
#define BM 128
#define BN 128
#define BK 16

template <int AMODE, int BMODE, int EPI>
__global__ __launch_bounds__(256, 2)
void gemm_kernel(const float* __restrict__ A, const float* __restrict__ B,
                 float* __restrict__ C, int M, int N, int K,
                 const float* __restrict__ bias, const float* __restrict__ extra,
                 const int* __restrict__ idxa, const int* __restrict__ idxb) {
    __shared__ float As[BK][BM];
    __shared__ float Bs[BK][BN];

    int tid = threadIdx.x;
    int tx = tid & 15;       // n: tx*4 and 64+tx*4
    int ty = tid >> 4;       // m: ty*4 and 64+ty*4
    int m0 = blockIdx.y * BM;
    int n0 = blockIdx.x * BN;

    ull acc[8][4];           // [m 8][n-pair 4], each 2 fp32
    #pragma unroll
    for (int r = 0; r < 8; r++)
        #pragma unroll
        for (int c = 0; c < 4; c++) acc[r][c] = 0ull;

    for (int k0 = 0; k0 < K; k0 += BK) {
        // A tile: 128 x 16 = 512 float4, 2 per thread
        #pragma unroll
        for (int it = 0; it < 2; it++) {
            int s = tid + it * 256;
            int m = s >> 2;
            int k4 = (s & 3) * 4;
            float4 av;
            if (AMODE == 0) {
                av = *(const float4*)(A + (size_t)(m0 + m) * K + k0 + k4);
            } else {
                int mg = m0 + m;
                int e = mg >> 3, l = mg & 7;
                const float4 u = *(const float4*)(A + (size_t)idxa[e] * FD + l * DD + k0 + k4);
                const float4 w = *(const float4*)(A + (size_t)idxb[e] * FD + l * DD + k0 + k4);
                av = make_float4(u.x + w.x, u.y + w.y, u.z + w.z, u.w + w.w);
            }
            As[k4 + 0][m] = av.x;
            As[k4 + 1][m] = av.y;
            As[k4 + 2][m] = av.z;
            As[k4 + 3][m] = av.w;
        }
        // B tile: 16 x 128 = 512 float4, 2 per thread
        #pragma unroll
        for (int it = 0; it < 2; it++) {
            int s = tid + it * 256;
            if (BMODE == 0) {
                int k = s >> 5;
                int n4 = (s & 31) * 4;
                float4 bv = make_float4(0.f, 0.f, 0.f, 0.f);
                if (n0 + n4 < N)
                    bv = *(const float4*)(B + (size_t)(k0 + k) * N + n0 + n4);
                *(float4*)&Bs[k][n4] = bv;
            } else {
                int n = s >> 2;
                int k4 = (s & 3) * 4;
                float4 bv = make_float4(0.f, 0.f, 0.f, 0.f);
                if (n0 + n < N)
                    bv = *(const float4*)(B + (size_t)(n0 + n) * K + k0 + k4);
                Bs[k4 + 0][n] = bv.x;
                Bs[k4 + 1][n] = bv.y;
                Bs[k4 + 2][n] = bv.z;
                Bs[k4 + 3][n] = bv.w;
            }
        }
        __syncthreads();

        #pragma unroll
        for (int kk = 0; kk < BK; kk++) {
            float4 a0 = *(const float4*)&As[kk][ty * 4];
            float4 a1 = *(const float4*)&As[kk][64 + ty * 4];
            ulonglong2 b0 = *(const ulonglong2*)&Bs[kk][tx * 4];
            ulonglong2 b1 = *(const ulonglong2*)&Bs[kk][64 + tx * 4];
            ull bv[4] = {b0.x, b0.y, b1.x, b1.y};
            ull ap[8];
            ap[0] = pack2(a0.x, a0.x); ap[1] = pack2(a0.y, a0.y);
            ap[2] = pack2(a0.z, a0.z); ap[3] = pack2(a0.w, a0.w);
            ap[4] = pack2(a1.x, a1.x); ap[5] = pack2(a1.y, a1.y);
            ap[6] = pack2(a1.z, a1.z); ap[7] = pack2(a1.w, a1.w);
            #pragma unroll
            for (int r = 0; r < 8; r++)
                #pragma unroll
                for (int c = 0; c < 4; c++)
                    acc[r][c] = fma2(ap[r], bv[c], acc[r][c]);
        }
        __syncthreads();
    }

    // ---- epilogue ----
    #pragma unroll
    for (int r = 0; r < 8; r++) {
        int m = m0 + (r >> 2) * 64 + ty * 4 + (r & 3);
        #pragma unroll
        for (int jn = 0; jn < 2; jn++) {
            int n = n0 + jn * 64 + tx * 4;
            if (n < N) {
                float v[4];
                unpack2(acc[r][jn * 2 + 0], v[0], v[1]);
                unpack2(acc[r][jn * 2 + 1], v[2], v[3]);
                #pragma unroll
                for (int j = 0; j < 4; j++) {
                    float x = v[j];
                    if (EPI == 1) x += bias[n + j];
                    else if (EPI == 2) { x += extra[(size_t)m * N + n + j]; x = fmaxf(x, 0.0f); }
                    else if (EPI == 3) { x += extra[(size_t)idxa[m] * N + n + j]; x = fmaxf(x, 0.0f); }
                    else if (EPI == 4) { x += extra[(size_t)m * N + n + j]; }
                    else if (EPI == 5) {
                        float c3 = x + 0.044715f * x * x * x;
                        x = 0.5f * x * (1.0f + tanhf(0.7978845608028654f * c3));
                    }
                    v[j] = x;
                }
                *(float4*)(C + (size_t)m * N + n) = make_float4(v[0], v[1], v[2], v[3]);
            }
        }
    }
}

// ---------------- per-(edge,head) attention: one warp each ----------------
__global__ void attn_kernel(const float* __restrict__ q, const float* __restrict__ k,
                            const float* __restrict__ v, float* __restrict__ o) {
    int b = blockIdx.x;
    int h = threadIdx.x >> 5;
    int lane = threadIdx.x & 31;
    int d0 = lane * 2;

    const size_t base = (size_t)b * LL * DG + h * 64 + d0;
    float qr[LL][2], kr[LL][2], vr[LL][2];
    #pragma unroll
    for (int i = 0; i < LL; i++) {
        qr[i][0] = q[base + (size_t)i * DG];     qr[i][1] = q[base + (size_t)i * DG + 1];
        kr[i][0] = k[base + (size_t)i * DG];     kr[i][1] = k[base + (size_t)i * DG + 1];
        vr[i][0] = v[base + (size_t)i * DG];     vr[i][1] = v[base + (size_t)i * DG + 1];
    }

    float att[LL][LL];
    #pragma unroll
    for (int i = 0; i < LL; i++)
        #pragma unroll
        for (int j = 0; j < LL; j++) {
            float p = qr[i][0] * kr[j][0] + qr[i][1] * kr[j][1];
            #pragma unroll
            for (int off = 16; off > 0; off >>= 1)
                p += __shfl_xor_sync(0xffffffffu, p, off);
            att[i][j] = p * 0.125f;
        }

    #pragma unroll
    for (int i = 0; i < LL; i++) {
        float mx = att[i][0];
        #pragma unroll
        for (int j = 1; j < LL; j++) mx = fmaxf(mx, att[i][j]);
        float s = 0.0f;
        #pragma unroll
        for (int j = 0; j < LL; j++) { att[i][j] = expf(att[i][j] - mx); s += att[i][j]; }
        float inv = 1.0f / s;
        float o0 = 0.0f, o1 = 0.0f;
        #pragma unroll
        for (int j = 0; j < LL; j++) {
            float a = att[i][j] * inv;
            o0 = fmaf(a, vr[j][0], o0);
            o1 = fmaf(a, vr[j][1], o1);
        }
        o[base + (size_t)i * DG] = o0;
        o[base + (size_t)i * DG + 1] = o1;
    }
}

// ---------------- final softmax over V per row (float4 vectorized) ----------------
#define NF4 2500   // VV/4

__global__ __launch_bounds__(256)
void lm_softmax_kernel(const float* __restrict__ logits, float* __restrict__ probs) {
    int r = blockIdx.x;
    int t = threadIdx.x;
    const float4* row = (const float4*)(logits + (size_t)r * VV);
    float4* orow = (float4*)(probs + (size_t)r * VV);

    float4 vals[10];
    float mx = -INFINITY;
    #pragma unroll
    for (int i = 0; i < 10; i++) {
        int c = t + i * 256;
        if (c < NF4) {
            float4 v = row[c];
            vals[i] = v;
            mx = fmaxf(mx, fmaxf(fmaxf(v.x, v.y), fmaxf(v.z, v.w)));
        }
    }
    __shared__ float sred[8];
    #pragma unroll
    for (int off = 16; off > 0; off >>= 1) mx = fmaxf(mx, __shfl_xor_sync(0xffffffffu, mx, off));
    if ((t & 31) == 0) sred[t >> 5] = mx;
    __syncthreads();
    if (t < 32) {
        float v2 = (t < 8) ? sred[t] : -INFINITY;
        #pragma unroll
        for (int off = 4; off > 0; off >>= 1) v2 = fmaxf(v2, __shfl_xor_sync(0xffffffffu, v2, off));
        if (t == 0) sred[0] = v2;
    }
    __syncthreads();
    mx = sred[0];
    __syncthreads();

    float s = 0.0f;
    #pragma unroll
    for (int i = 0; i < 10; i++) {
        int c = t + i * 256;
        if (c < NF4) {
            float4 v = vals[i];
            v.x = __expf(v.x - mx); v.y = __expf(v.y - mx);
            v.z = __expf(v.z - mx); v.w = __expf(v.w - mx);
            vals[i] = v;
            s += v.x + v.y + v.z + v.w;
        }
    }
    #pragma unroll
    for (int off = 16; off > 0; off >>= 1) s += __shfl_xor_sync(0xffffffffu, s, off);
    if ((t & 31) == 0) sred[t >> 5] = s;
    __syncthreads();
    if (t < 32) {
        float v2 = (t < 8) ? sred[t] : 0.0f;
        #pragma unroll
        for (int off = 4; off > 0; off >>= 1) v2 += __shfl_xor_sync(0xffffffffu, v2, off);
        if (t == 0) sred[0] = v2;
    }
    __syncthreads();
    float inv = 1.0f / sred[0];

    #pragma unroll
    for (int i = 0; i < 10; i++) {
        int c = t + i * 256;
        if (c < NF4) {
            float4 v = vals[i];
            v.x *= inv; v.y *= inv; v.z *= inv; v.w *= inv;
            orow[c] = v;
        }
    }
}

// ---------------- host launch ----------------
extern "C" void kernel_launch(void* const* d_in, const int* in_sizes, int n_in,
                              void* d_out, int out_size) {
    const int* node_tokens = (const int*)d_in[0];
    const int* edge_tokens = (const int*)d_in[1];
    const int* edge_index  = (const int*)d_in[2];
    const int* mask_rows   = (const int*)d_in[3];
    const float* emb    = (const float*)d_in[4];
    const float* W_msg  = (const float*)d_in[5];
    const float* W_node = (const float*)d_in[6];
    const float* lc1_w  = (const float*)d_in[7];
    const float* lc1_b  = (const float*)d_in[8];
    const float* lc2_w  = (const float*)d_in[9];
    const float* lc2_b  = (const float*)d_in[10];
    const float* Wq  = (const float*)d_in[11];
    const float* Wk  = (const float*)d_in[12];
    const float* Wv  = (const float*)d_in[13];
    const float* Wo  = (const float*)d_in[14];
    const float* Wf1 = (const float*)d_in[15];
    const float* Wf2 = (const float*)d_in[16];

    const int* src = edge_index;
    const int* dst = edge_index + NE;

    float* out = (float*)d_out;
    float* labels_ptr = nullptr;
    float* probs_ptr  = nullptr;
    long total = (long)NTOK * VV;
    if ((long)out_size >= total + NTOK) { labels_ptr = out; probs_ptr = out + NTOK; }
    else if ((long)out_size >= total)   { probs_ptr = out; }
    else                                { labels_ptr = out; }

    void *px, *pe, *pmsg, *pagg, *ph, *pz, *pq, *pk, *pv, *pattn, *px1, *pffn, *px2, *py, *plog;
    cudaGetSymbolAddress(&px, g_x);      cudaGetSymbolAddress(&pe, g_e);
    cudaGetSymbolAddress(&pmsg, g_msg);  cudaGetSymbolAddress(&pagg, g_agg);
    cudaGetSymbolAddress(&ph, g_h);      cudaGetSymbolAddress(&pz, g_z);
    cudaGetSymbolAddress(&pq, g_q);      cudaGetSymbolAddress(&pk, g_k);
    cudaGetSymbolAddress(&pv, g_v);      cudaGetSymbolAddress(&pattn, g_attn);
    cudaGetSymbolAddress(&px1, g_x1);    cudaGetSymbolAddress(&pffn, g_ffn);
    cudaGetSymbolAddress(&px2, g_x2);    cudaGetSymbolAddress(&py, g_y);
    cudaGetSymbolAddress(&plog, g_logits);
    float *X = (float*)px, *E = (float*)pe, *MSG = (float*)pmsg, *AGG = (float*)pagg;
    float *H = (float*)ph, *Z = (float*)pz, *Q = (float*)pq, *Kb = (float*)pk, *Vb = (float*)pv;
    float *AT = (float*)pattn, *X1 = (float*)px1, *FFN = (float*)pffn, *X2 = (float*)px2;
    float *Y = (float*)py, *LOG = (float*)plog;

    // 1. embeddings (+ zero agg early)
    node_embed_kernel<<<(NN * FD + 255) / 256, 256>>>(node_tokens, emb, X);
    edge_mask_embed_kernel<<<NE, 256>>>(edge_tokens, mask_rows, emb, E, labels_ptr);

    if (probs_ptr == nullptr) return;

    zero_kernel<<<(NN * FD + 255) / 256, 256>>>(AGG, NN * FD);
    // 2. msg = relu(e @ W_msg + x[src])
    gemm_kernel<0, 0, 3><<<dim3(FD / BN, NE / BM), 256>>>(E, W_msg, MSG, NE, FD, FD,
                                                          nullptr, X, src, nullptr);
    // 3. agg = segment_sum(msg, dst)
    scatter_add_kernel<<<(NE * FD + 255) / 256, 256>>>(MSG, dst, AGG);
    // 4. h = relu(x @ W_node + agg)
    gemm_kernel<0, 0, 2><<<dim3(FD / BN, NN / BM), 256>>>(X, W_node, H, NN, FD, FD,
                                                          nullptr, AGG, nullptr, nullptr);
    // 5. z = (h[src]+h[dst]).reshape(.,L,D) @ lc1_w + lc1_b
    gemm_kernel<1, 0, 1><<<dim3(DG / BN, NTOK / BM), 256>>>(H, lc1_w, Z, NTOK, DG, DD,
                                                            lc1_b, nullptr, src, dst);
    // 6. q, k, v
    gemm_kernel<0, 0, 0><<<dim3(DG / BN, NTOK / BM), 256>>>(Z, Wq, Q, NTOK, DG, DG,
                                                            nullptr, nullptr, nullptr, nullptr);
    gemm_kernel<0, 0, 0><<<dim3(DG / BN, NTOK / BM), 256>>>(Z, Wk, Kb, NTOK, DG, DG,
                                                            nullptr, nullptr, nullptr, nullptr);
    gemm_kernel<0, 0, 0><<<dim3(DG / BN, NTOK / BM), 256>>>(Z, Wv, Vb, NTOK, DG, DG,
                                                            nullptr, nullptr, nullptr, nullptr);
    // 7. attention
    attn_kernel<<<NE, 128>>>(Q, Kb, Vb, AT);
    // 8. x1 = z + attn @ Wo
    gemm_kernel<0, 0, 4><<<dim3(DG / BN, NTOK / BM), 256>>>(AT, Wo, X1, NTOK, DG, DG,
                                                            nullptr, Z, nullptr, nullptr);
    // 9. ffn = gelu(x1 @ Wf1)
    gemm_kernel<0, 0, 5><<<dim3(4 * DG / BN, NTOK / BM), 256>>>(X1, Wf1, FFN, NTOK, 4 * DG, DG,
                                                                nullptr, nullptr, nullptr, nullptr);
    // 10. x2 = x1 + ffn @ Wf2
    gemm_kernel<0, 0, 4><<<dim3(DG / BN, NTOK / BM), 256>>>(FFN, Wf2, X2, NTOK, DG, 4 * DG,
                                                            nullptr, X1, nullptr, nullptr);
    // 11. y = x2 @ lc2_w + lc2_b
    gemm_kernel<0, 0, 1><<<dim3(1, NTOK / BM), 256>>>(X2, lc2_w, Y, NTOK, DD, DG,
                                                      lc2_b, nullptr, nullptr, nullptr);
    // 12. logits = y @ emb.T   (B stored [V, D] -> BMODE 1)
    gemm_kernel<0, 1, 0><<<dim3((VV + BN - 1) / BN, NTOK / BM), 256>>>(Y, emb, LOG, NTOK, VV, DD,
                                                                       nullptr, nullptr, nullptr, nullptr);
    // 13. probs = softmax(logits)
    lm_softmax_kernel<<<NTOK, 256>>>(LOG, probs_ptr);
}

// round 7
// speedup vs baseline: 1.5206x; 1.0662x over previous
#include <cuda_runtime.h>
#include <cuda_bf16.h>
#include <math.h>
#include <stdint.h>

// Problem constants
#define NN 8192      // nodes
#define NE 2048      // edges
#define LL 8         // tokens per node/edge
#define DD 64        // gnn hidden
#define FD 512       // LL*DD
#define DG 256       // gpt hidden
#define VV 10000     // vocab
#define NTOK 16384   // NE*LL

// ---------------- device scratch (static, allocation-free) ----------------
__device__ float g_x[NN * FD];
__device__ float g_e[NE * FD];
__device__ float g_msg[NE * FD];
__device__ float g_agg[NN * FD];
__device__ float g_h[NN * FD];
__device__ float g_z[NTOK * DG];
__device__ float g_q[NTOK * DG];
__device__ float g_k[NTOK * DG];
__device__ float g_v[NTOK * DG];
__device__ float g_attn[NTOK * DG];
__device__ float g_x1[NTOK * DG];
__device__ float g_ffn[NTOK * 4 * DG];
__device__ float g_x2[NTOK * DG];
__device__ float g_y[NTOK * DD];
__device__ float g_logits[(size_t)NTOK * VV];   // 655 MB

// ---------------- small kernels ----------------

__global__ void zero_kernel(float* __restrict__ p, int n) {
    int i = blockIdx.x * blockDim.x + threadIdx.x;
    if (i < n) p[i] = 0.0f;
}

__global__ void node_embed_kernel(const int* __restrict__ ntok,
                                  const float* __restrict__ emb,
                                  float* __restrict__ x) {
    int i = blockIdx.x * blockDim.x + threadIdx.x;
    if (i < NN * FD) {
        int row = i >> 9;
        int col = i & 511;
        int l = col >> 6, d = col & 63;
        x[i] = emb[(size_t)ntok[row * LL + l] * DD + d];
    }
}

__global__ void edge_mask_embed_kernel(const int* __restrict__ etok,
                                       const int* __restrict__ mask_rows,
                                       const float* __restrict__ emb,
                                       float* __restrict__ e_out,
                                       float* __restrict__ labels_out) {
    int b = blockIdx.x;
    __shared__ int mt[LL];
    int t = threadIdx.x;
    if (t < LL) {
        int tok = etok[b * LL + t];
        bool special = ((unsigned)tok) < 4u;
        bool masked = (mask_rows[b] != 0) && !special;
        mt[t] = masked ? 4 : tok;
        if (labels_out) labels_out[b * LL + t] = masked ? (float)tok : -100.0f;
    }
    __syncthreads();
    for (int c = t; c < FD; c += blockDim.x) {
        int l = c >> 6, d = c & 63;
        e_out[(size_t)b * FD + c] = emb[(size_t)mt[l] * DD + d];
    }
}

__global__ void scatter_add_kernel(const float* __restrict__ msg,
                                   const int* __restrict__ dst,
                                   float* __restrict__ agg) {
    int i = blockIdx.x * blockDim.x + threadIdx.x;
    if (i < NE * FD) {
        int e = i >> 9;
        int n = i & 511;
        atomicAdd(&agg[(size_t)dst[e] * FD + n], msg[i]);
    }
}

// ================= mma.sync helpers (sm_80-era, valid on base sm_103) =========

__device__ __forceinline__ uint32_t cvta_shared_u32(const void* p) {
    return (uint32_t)__cvta_generic_to_shared(p);
}

__device__ __forceinline__ void ldm_x4(uint32_t* r, uint32_t addr) {
    asm volatile("ldmatrix.sync.aligned.m8n8.x4.shared.b16 {%0,%1,%2,%3}, [%4];"
                 : "=r"(r[0]), "=r"(r[1]), "=r"(r[2]), "=r"(r[3]) : "r"(addr));
}

__device__ __forceinline__ void mma16816(float* c, const uint32_t* a,
                                         uint32_t b0, uint32_t b1) {
    asm volatile(
        "mma.sync.aligned.m16n8k16.row.col.f32.bf16.bf16.f32 "
        "{%0,%1,%2,%3}, {%4,%5,%6,%7}, {%8,%9}, {%0,%1,%2,%3};"
        : "+f"(c[0]), "+f"(c[1]), "+f"(c[2]), "+f"(c[3])
        : "r"(a[0]), "r"(a[1]), "r"(a[2]), "r"(a[3]), "r"(b0), "r"(b1));
}

// pack 2 floats -> bf16x2 (x0 in low half)
__device__ __forceinline__ uint32_t bf2pack(float x0, float x1) {
    __nv_bfloat162 h = __floats2bfloat162_rn(x0, x1);
    return *(uint32_t*)&h;
}

// hi/lo split of 8 floats
__device__ __forceinline__ void split8(const float* f, float* h, float* l) {
    #pragma unroll
    for (int j = 0; j < 8; j++) {
        float hf = __bfloat162float(__float2bfloat16_rn(f[j]));
        h[j] = hf;
        l[j] = f[j] - hf;
    }
}

__device__ __forceinline__ uint4 pack8(const float* v) {
    return make_uint4(bf2pack(v[0], v[1]), bf2pack(v[2], v[3]),
                      bf2pack(v[4], v[5]), bf2pack(v[6], v[7]));
}

// ================= HMMA GEMM: 128x128 tile, K chunks of 32 ===================
// C[M,N] = epi(A[M,K] @ B[K,N]) via bf16 hi/lo 3-MMA split (rel err ~3e-5)
// AMODE 0: A row-major [M,K].  AMODE 1: A row m = h[src[e]]+h[dst[e]] slice.
// BMODE 0: B row-major [K,N].  BMODE 1: B stored [N,K] row-major.
// EPI: 0 none, 1 +bias[n], 2 relu(.+extra[m,n]), 3 relu(.+extra[idxa[m],n]),
//      4 .+extra[m,n], 5 gelu tanh
// Grid: (ceil(N/128), M/128). 256 threads. M%128==0, K%32==0 required.

#define PITCH 40   // bf16 elements per smem row (32 + 8 pad); 80 bytes

template <int AMODE, int BMODE, int EPI>
__global__ __launch_bounds__(256, 2)
void gemm_mma(const float* __restrict__ A, const float* __restrict__ B,
              float* __restrict__ C, int M, int N, int K,
              const float* __restrict__ bias, const float* __restrict__ extra,
              const int* __restrict__ idxa, const int* __restrict__ idxb) {
    __shared__ __nv_bfloat16 sAh[128 * PITCH], sAl[128 * PITCH];
    __shared__ __nv_bfloat16 sBh[128 * PITCH], sBl[128 * PITCH];

    const int tid = threadIdx.x;
    const int lane = tid & 31;
    const int w = tid >> 5;
    const int m0 = blockIdx.y * 128;
    const int n0 = blockIdx.x * 128;
    const int wm = (w & 3) * 32;    // warp m-offset within tile
    const int wn = (w >> 2) * 64;   // warp n-offset within tile

    const uint32_t aAh = cvta_shared_u32(sAh);
    const uint32_t aAl = cvta_shared_u32(sAl);
    const uint32_t aBh = cvta_shared_u32(sBh);
    const uint32_t aBl = cvta_shared_u32(sBl);

    float c[2][8][4];
    #pragma unroll
    for (int mi = 0; mi < 2; mi++)
        #pragma unroll
        for (int nj = 0; nj < 8; nj++)
            #pragma unroll
            for (int q = 0; q < 4; q++) c[mi][nj][q] = 0.0f;

    for (int k0 = 0; k0 < K; k0 += 32) {
        // ---- load A chunk: 128 rows x 32 k ----
        #pragma unroll
        for (int i = 0; i < 2; i++) {
            int u = tid + i * 256;           // 0..511
            int r = u >> 2, ks = (u & 3) * 8;
            float f[8];
            if (AMODE == 0) {
                const float4* p = (const float4*)(A + (size_t)(m0 + r) * K + k0 + ks);
                float4 a = p[0], b = p[1];
                f[0]=a.x; f[1]=a.y; f[2]=a.z; f[3]=a.w;
                f[4]=b.x; f[5]=b.y; f[6]=b.z; f[7]=b.w;
            } else {
                int mg = m0 + r;
                int e = mg >> 3, l = mg & 7;
                const float4* pa = (const float4*)(A + (size_t)idxa[e] * FD + l * DD + k0 + ks);
                const float4* pb = (const float4*)(A + (size_t)idxb[e] * FD + l * DD + k0 + ks);
                float4 a0 = pa[0], a1 = pa[1], b0 = pb[0], b1 = pb[1];
                f[0]=a0.x+b0.x; f[1]=a0.y+b0.y; f[2]=a0.z+b0.z; f[3]=a0.w+b0.w;
                f[4]=a1.x+b1.x; f[5]=a1.y+b1.y; f[6]=a1.z+b1.z; f[7]=a1.w+b1.w;
            }
            float h[8], l8[8];
            split8(f, h, l8);
            *(uint4*)((char*)sAh + r * (PITCH*2) + ks * 2) = pack8(h);
            *(uint4*)((char*)sAl + r * (PITCH*2) + ks * 2) = pack8(l8);
        }
        // ---- load B chunk into smem as [n][k] ----
        if (BMODE == 0) {
            // global [K,N]: coalesced along n, scatter into smem rows
            #pragma unroll
            for (int i = 0; i < 2; i++) {
                int u = tid + i * 256;
                int k = u >> 4, ns = (u & 15) * 8;
                float f[8];
                if (n0 + ns + 8 <= N) {
                    const float4* p = (const float4*)(B + (size_t)(k0 + k) * N + n0 + ns);
                    float4 a = p[0], b = p[1];
                    f[0]=a.x; f[1]=a.y; f[2]=a.z; f[3]=a.w;
                    f[4]=b.x; f[5]=b.y; f[6]=b.z; f[7]=b.w;
                } else {
                    #pragma unroll
                    for (int j = 0; j < 8; j++)
                        f[j] = (n0 + ns + j < N) ? B[(size_t)(k0 + k) * N + n0 + ns + j] : 0.0f;
                }
                float h[8], l8[8];
                split8(f, h, l8);
                #pragma unroll
                for (int j = 0; j < 8; j++) {
                    sBh[(ns + j) * PITCH + k] = __float2bfloat16_rn(h[j]);
                    sBl[(ns + j) * PITCH + k] = __float2bfloat16_rn(l8[j]);
                }
            }
        } else {
            // global [N,K]: same pattern as A
            #pragma unroll
            for (int i = 0; i < 2; i++) {
                int u = tid + i * 256;
                int r = u >> 2, ks = (u & 3) * 8;
                float f[8];
                if (n0 + r < N) {
                    const float4* p = (const float4*)(B + (size_t)(n0 + r) * K + k0 + ks);
                    float4 a = p[0], b = p[1];
                    f[0]=a.x; f[1]=a.y; f[2]=a.z; f[3]=a.w;
                    f[4]=b.x; f[5]=b.y; f[6]=b.z; f[7]=b.w;
                } else {
                    #pragma unroll
                    for (int j = 0; j < 8; j++) f[j] = 0.0f;
                }
                float h[8], l8[8];
                split8(f, h, l8);
                *(uint4*)((char*)sBh + r * (PITCH*2) + ks * 2) = pack8(h);
                *(uint4*)((char*)sBl + r * (PITCH*2) + ks * 2) = pack8(l8);
            }
        }
        __syncthreads();

        // ---- compute: 2 k16 steps ----
        #pragma unroll
        for (int kk = 0; kk < 2; kk++) {
            const int kc = kk * 16;
            const uint32_t ld_off = (((lane & 15)) * PITCH + ((lane >> 4) * 8 + kc)) * 2;
            uint32_t ah[2][4], al[2][4];
            #pragma unroll
            for (int mi = 0; mi < 2; mi++) {
                uint32_t rowoff = (wm + mi * 16) * (PITCH * 2);
                ldm_x4(ah[mi], aAh + rowoff + ld_off);
                ldm_x4(al[mi], aAl + rowoff + ld_off);
            }
            uint32_t bh[4][4], bl[4][4];
            #pragma unroll
            for (int ni = 0; ni < 4; ni++) {
                uint32_t rowoff = (wn + ni * 16) * (PITCH * 2);
                ldm_x4(bh[ni], aBh + rowoff + ld_off);
                ldm_x4(bl[ni], aBl + rowoff + ld_off);
            }
            #pragma unroll
            for (int mi = 0; mi < 2; mi++) {
                #pragma unroll
                for (int nj = 0; nj < 8; nj++) {
                    int ni = nj >> 1, half = nj & 1;
                    uint32_t bh0 = bh[ni][half], bh1 = bh[ni][half + 2];
                    uint32_t bl0 = bl[ni][half], bl1 = bl[ni][half + 2];
                    mma16816(c[mi][nj], ah[mi], bh0, bh1);   // Ah*Bh
                    mma16816(c[mi][nj], ah[mi], bl0, bl1);   // Ah*Bl
                    mma16816(c[mi][nj], al[mi], bh0, bh1);   // Al*Bh
                }
            }
        }
        __syncthreads();
    }

    // ---- epilogue ----
    const int gr = lane >> 2;          // 0..7
    const int gc = (lane & 3) * 2;     // 0,2,4,6
    #pragma unroll
    for (int mi = 0; mi < 2; mi++) {
        #pragma unroll
        for (int nj = 0; nj < 8; nj++) {
            int n = n0 + wn + nj * 8 + gc;
            if (n >= N) continue;
            #pragma unroll
            for (int half = 0; half < 2; half++) {
                int m = m0 + wm + mi * 16 + gr + half * 8;
                float v0 = c[mi][nj][half * 2 + 0];
                float v1 = c[mi][nj][half * 2 + 1];
                if (EPI == 1) { v0 += bias[n]; v1 += bias[n + 1]; }
                else if (EPI == 2) {
                    v0 += extra[(size_t)m * N + n];     v0 = fmaxf(v0, 0.0f);
                    v1 += extra[(size_t)m * N + n + 1]; v1 = fmaxf(v1, 0.0f);
                } else if (EPI == 3) {
                    size_t rb = (size_t)idxa[m] * N;
                    v0 += extra[rb + n];     v0 = fmaxf(v0, 0.0f);
                    v1 += extra[rb + n + 1]; v1 = fmaxf(v1, 0.0f);
                } else if (EPI == 4) {
                    v0 += extra[(size_t)m * N + n];
                    v1 += extra[(size_t)m * N + n + 1];
                } else if (EPI == 5) {
                    float c3 = v0 + 0.044715f * v0 * v0 * v0;
                    v0 = 0.5f * v0 * (1.0f + tanhf(0.7978845608028654f * c3));
                    c3 = v1 + 0.044715f * v1 * v1 * v1;
                    v1 = 0.5f * v1 * (1.0f + tanhf(0.7978845608028654f * c3));
                }
                *(float2*)(C + (size_t)m * N + n) = make_float2(v0, v1);
            }
        }
    }
}

// ---------------- per-(edge,head) attention: one warp each ----------------
__global__ void attn_kernel(const float* __restrict__ q, const float* __restrict__ k,
                            const float* __restrict__ v, float* __restrict__ o) {
    int b = blockIdx.x;
    int h = threadIdx.x >> 5;
    int lane = threadIdx.x & 31;
    int d0 = lane * 2;

    const size_t base = (size_t)b * LL * DG + h * 64 + d0;
    float qr[LL][2], kr[LL][2], vr[LL][2];
    #pragma unroll
    for (int i = 0; i < LL; i++) {
        qr[i][0] = q[base + (size_t)i * DG];     qr[i][1] = q[base + (size_t)i * DG + 1];
        kr[i][0] = k[base + (size_t)i * DG];     kr[i][1] = k[base + (size_t)i * DG + 1];
        vr[i][0] = v[base + (size_t)i * DG];     vr[i][1] = v[base + (size_t)i * DG + 1];
    }

    float att[LL][LL];
    #pragma unroll
    for (int i = 0; i < LL; i++)
        #pragma unroll
        for (int j = 0; j < LL; j++) {
            float p = qr[i][0] * kr[j][0] + qr[i][1] * kr[j][1];
            #pragma unroll
            for (int off = 16; off > 0; off >>= 1)
                p += __shfl_xor_sync(0xffffffffu, p, off);
            att[i][j] = p * 0.125f;
        }

    #pragma unroll
    for (int i = 0; i < LL; i++) {
        float mx = att[i][0];
        #pragma unroll
        for (int j = 1; j < LL; j++) mx = fmaxf(mx, att[i][j]);
        float s = 0.0f;
        #pragma unroll
        for (int j = 0; j < LL; j++) { att[i][j] = expf(att[i][j] - mx); s += att[i][j]; }
        float inv = 1.0f / s;
        float o0 = 0.0f, o1 = 0.0f;
        #pragma unroll
        for (int j = 0; j < LL; j++) {
            float a = att[i][j] * inv;
            o0 = fmaf(a, vr[j][0], o0);
            o1 = fmaf(a, vr[j][1], o1);
        }
        o[base + (size_t)i * DG] = o0;
        o[base + (size_t)i * DG + 1] = o1;
    }
}

// ---------------- final softmax over V per row (float4 vectorized) ----------------
#define NF4 2500   // VV/4

__global__ __launch_bounds__(256)
void lm_softmax_kernel(const float* __restrict__ logits, float* __restrict__ probs) {
    int r = blockIdx.x;
    int t = threadIdx.x;
    const float4* row = (const float4*)(logits + (size_t)r * VV);
    float4* orow = (float4*)(probs + (size_t)r * VV);

    float4 vals[10];
    float mx = -INFINITY;
    #pragma unroll
    for (int i = 0; i < 10; i++) {
        int c = t + i * 256;
        if (c < NF4) {
            float4 v = row[c];
            vals[i] = v;
            mx = fmaxf(mx, fmaxf(fmaxf(v.x, v.y), fmaxf(v.z, v.w)));
        }
    }
    __shared__ float sred[8];
    #pragma unroll
    for (int off = 16; off > 0; off >>= 1) mx = fmaxf(mx, __shfl_xor_sync(0xffffffffu, mx, off));
    if ((t & 31) == 0) sred[t >> 5] = mx;
    __syncthreads();
    if (t < 32) {
        float v2 = (t < 8) ? sred[t] : -INFINITY;
        #pragma unroll
        for (int off = 4; off > 0; off >>= 1) v2 = fmaxf(v2, __shfl_xor_sync(0xffffffffu, v2, off));
        if (t == 0) sred[0] = v2;
    }
    __syncthreads();
    mx = sred[0];
    __syncthreads();

    float s = 0.0f;
    #pragma unroll
    for (int i = 0; i < 10; i++) {
        int c = t + i * 256;
        if (c < NF4) {
            float4 v = vals[i];
            v.x = __expf(v.x - mx); v.y = __expf(v.y - mx);
            v.z = __expf(v.z - mx); v.w = __expf(v.w - mx);
            vals[i] = v;
            s += v.x + v.y + v.z + v.w;
        }
    }
    #pragma unroll
    for (int off = 16; off > 0; off >>= 1) s += __shfl_xor_sync(0xffffffffu, s, off);
    if ((t & 31) == 0) sred[t >> 5] = s;
    __syncthreads();
    if (t < 32) {
        float v2 = (t < 8) ? sred[t] : 0.0f;
        #pragma unroll
        for (int off = 4; off > 0; off >>= 1) v2 += __shfl_xor_sync(0xffffffffu, v2, off);
        if (t == 0) sred[0] = v2;
    }
    __syncthreads();
    float inv = 1.0f / sred[0];

    #pragma unroll
    for (int i = 0; i < 10; i++) {
        int c = t + i * 256;
        if (c < NF4) {
            float4 v = vals[i];
            v.x *= inv; v.y *= inv; v.z *= inv; v.w *= inv;
            orow[c] = v;
        }
    }
}

// ---------------- host launch ----------------
extern "C" void kernel_launch(void* const* d_in, const int* in_sizes, int n_in,
                              void* d_out, int out_size) {
    const int* node_tokens = (const int*)d_in[0];
    const int* edge_tokens = (const int*)d_in[1];
    const int* edge_index  = (const int*)d_in[2];
    const int* mask_rows   = (const int*)d_in[3];
    const float* emb    = (const float*)d_in[4];
    const float* W_msg  = (const float*)d_in[5];
    const float* W_node = (const float*)d_in[6];
    const float* lc1_w  = (const float*)d_in[7];
    const float* lc1_b  = (const float*)d_in[8];
    const float* lc2_w  = (const float*)d_in[9];
    const float* lc2_b  = (const float*)d_in[10];
    const float* Wq  = (const float*)d_in[11];
    const float* Wk  = (const float*)d_in[12];
    const float* Wv  = (const float*)d_in[13];
    const float* Wo  = (const float*)d_in[14];
    const float* Wf1 = (const float*)d_in[15];
    const float* Wf2 = (const float*)d_in[16];

    const int* src = edge_index;
    const int* dst = edge_index + NE;

    float* out = (float*)d_out;
    float* labels_ptr = nullptr;
    float* probs_ptr  = nullptr;
    long total = (long)NTOK * VV;
    if ((long)out_size >= total + NTOK) { labels_ptr = out; probs_ptr = out + NTOK; }
    else if ((long)out_size >= total)   { probs_ptr = out; }
    else                                { labels_ptr = out; }

    void *px, *pe, *pmsg, *pagg, *ph, *pz, *pq, *pk, *pv, *pattn, *px1, *pffn, *px2, *py, *plog;
    cudaGetSymbolAddress(&px, g_x);      cudaGetSymbolAddress(&pe, g_e);
    cudaGetSymbolAddress(&pmsg, g_msg);  cudaGetSymbolAddress(&pagg, g_agg);
    cudaGetSymbolAddress(&ph, g_h);      cudaGetSymbolAddress(&pz, g_z);
    cudaGetSymbolAddress(&pq, g_q);      cudaGetSymbolAddress(&pk, g_k);
    cudaGetSymbolAddress(&pv, g_v);      cudaGetSymbolAddress(&pattn, g_attn);
    cudaGetSymbolAddress(&px1, g_x1);    cudaGetSymbolAddress(&pffn, g_ffn);
    cudaGetSymbolAddress(&px2, g_x2);    cudaGetSymbolAddress(&py, g_y);
    cudaGetSymbolAddress(&plog, g_logits);
    float *X = (float*)px, *E = (float*)pe, *MSG = (float*)pmsg, *AGG = (float*)pagg;
    float *H = (float*)ph, *Z = (float*)pz, *Q = (float*)pq, *Kb = (float*)pk, *Vb = (float*)pv;
    float *AT = (float*)pattn, *X1 = (float*)px1, *FFN = (float*)pffn, *X2 = (float*)px2;
    float *Y = (float*)py, *LOG = (float*)plog;

    // 1. embeddings (+ zero agg early)
    node_embed_kernel<<<(NN * FD + 255) / 256, 256>>>(node_tokens, emb, X);
    edge_mask_embed_kernel<<<NE, 256>>>(edge_tokens, mask_rows, emb, E, labels_ptr);

    if (probs_ptr == nullptr) return;

    zero_kernel<<<(NN * FD + 255) / 256, 256>>>(AGG, NN * FD);
    // 2. msg = relu(e @ W_msg + x[src])
    gemm_mma<0,0,3><<<dim3(FD/128, NE/128), 256>>>(E, W_msg, MSG, NE, FD, FD,
                                                   nullptr, X, src, nullptr);
    // 3. agg = segment_sum(msg, dst)
    scatter_add_kernel<<<(NE * FD + 255) / 256, 256>>>(MSG, dst, AGG);
    // 4. h = relu(x @ W_node + agg)
    gemm_mma<0,0,2><<<dim3(FD/128, NN/128), 256>>>(X, W_node, H, NN, FD, FD,
                                                   nullptr, AGG, nullptr, nullptr);
    // 5. z = (h[src]+h[dst]).reshape(.,L,D) @ lc1_w + lc1_b
    gemm_mma<1,0,1><<<dim3(DG/128, NTOK/128), 256>>>(H, lc1_w, Z, NTOK, DG, DD,
                                                     lc1_b, nullptr, src, dst);
    // 6. q, k, v
    gemm_mma<0,0,0><<<dim3(DG/128, NTOK/128), 256>>>(Z, Wq, Q, NTOK, DG, DG,
                                                     nullptr, nullptr, nullptr, nullptr);
    gemm_mma<0,0,0><<<dim3(DG/128, NTOK/128), 256>>>(Z, Wk, Kb, NTOK, DG, DG,
                                                     nullptr, nullptr, nullptr, nullptr);
    gemm_mma<0,0,0><<<dim3(DG/128, NTOK/128), 256>>>(Z, Wv, Vb, NTOK, DG, DG,
                                                     nullptr, nullptr, nullptr, nullptr);
    // 7. attention
    attn_kernel<<<NE, 128>>>(Q, Kb, Vb, AT);
    // 8. x1 = z + attn @ Wo
    gemm_mma<0,0,4><<<dim3(DG/128, NTOK/128), 256>>>(AT, Wo, X1, NTOK, DG, DG,
                                                     nullptr, Z, nullptr, nullptr);
    // 9. ffn = gelu(x1 @ Wf1)
    gemm_mma<0,0,5><<<dim3(4*DG/128, NTOK/128), 256>>>(X1, Wf1, FFN, NTOK, 4*DG, DG,
                                                       nullptr, nullptr, nullptr, nullptr);
    // 10. x2 = x1 + ffn @ Wf2
    gemm_mma<0,0,4><<<dim3(DG/128, NTOK/128), 256>>>(FFN, Wf2, X2, NTOK, DG, 4*DG,
                                                     nullptr, X1, nullptr, nullptr);
    // 11. y = x2 @ lc2_w + lc2_b   (N=64 < 128-tile; guarded)
    gemm_mma<0,0,1><<<dim3(1, NTOK/128), 256>>>(X2, lc2_w, Y, NTOK, DD, DG,
                                                lc2_b, nullptr, nullptr, nullptr);
    // 12. logits = y @ emb.T   (B stored [V, D] -> BMODE 1)
    gemm_mma<0,1,0><<<dim3((VV+127)/128, NTOK/128), 256>>>(Y, emb, LOG, NTOK, VV, DD,
                                                           nullptr, nullptr, nullptr, nullptr);
    // 13. probs = softmax(logits)
    lm_softmax_kernel<<<NTOK, 256>>>(LOG, probs_ptr);
}

// round 9
// speedup vs baseline: 1.9510x; 1.2831x over previous
#include <cuda_runtime.h>
#include <cuda_bf16.h>
#include <math.h>
#include <stdint.h>

// Problem constants
#define NN 8192      // nodes
#define NE 2048      // edges
#define LL 8         // tokens per node/edge
#define DD 64        // gnn hidden
#define FD 512       // LL*DD
#define DG 256       // gpt hidden
#define VV 10000     // vocab
#define NTOK 16384   // NE*LL

typedef __nv_bfloat16 bf;

// ---------------- fp32 scratch ----------------
__device__ float g_x[NN * FD];
__device__ float g_msg[NE * FD];
__device__ float g_agg[NN * FD];
__device__ float g_h[NN * FD];
__device__ float g_z[NTOK * DG];
__device__ float g_qkv[NTOK * 3 * DG];
__device__ float g_x1[NTOK * DG];
__device__ float g_logits[(size_t)NTOK * VV];   // 655 MB

// ---------------- bf16 hi/lo planes ----------------
__device__ bf g_Xh[NN * FD],  g_Xl[NN * FD];
__device__ bf g_Eh[NE * FD],  g_El[NE * FD];
__device__ bf g_Zh[NTOK * DG], g_Zl[NTOK * DG];
__device__ bf g_ATh[NTOK * DG], g_ATl[NTOK * DG];
__device__ bf g_X1h[NTOK * DG], g_X1l[NTOK * DG];
__device__ bf g_FFh[NTOK * 4 * DG], g_FFl[NTOK * 4 * DG];
__device__ bf g_X2h[NTOK * DG], g_X2l[NTOK * DG];
__device__ bf g_Yh[NTOK * DD], g_Yl[NTOK * DD];
__device__ bf g_embh[VV * DD], g_embl[VV * DD];
// transposed weights [N][K]
__device__ bf g_WmsgTh[FD * FD],  g_WmsgTl[FD * FD];
__device__ bf g_WnodeTh[FD * FD], g_WnodeTl[FD * FD];
__device__ bf g_lc1Th[DG * DD],   g_lc1Tl[DG * DD];
__device__ bf g_qkvTh[3 * DG * DG], g_qkvTl[3 * DG * DG];
__device__ bf g_WoTh[DG * DG],    g_WoTl[DG * DG];
__device__ bf g_Wf1Th[4 * DG * DG], g_Wf1Tl[4 * DG * DG];
__device__ bf g_Wf2Th[DG * 4 * DG], g_Wf2Tl[DG * 4 * DG];
__device__ bf g_lc2Th[DD * DG],   g_lc2Tl[DD * DG];

// ---------------- helpers ----------------
__device__ __forceinline__ uint32_t bf2pack(float x0, float x1) {
    __nv_bfloat162 h = __floats2bfloat162_rn(x0, x1);
    return *(uint32_t*)&h;
}
__device__ __forceinline__ void split1(float v, bf& h, bf& l) {
    h = __float2bfloat16_rn(v);
    l = __float2bfloat16_rn(v - __bfloat162float(h));
}
__device__ __forceinline__ void split8(const float* f, float* h, float* l) {
    #pragma unroll
    for (int j = 0; j < 8; j++) {
        float hf = __bfloat162float(__float2bfloat16_rn(f[j]));
        h[j] = hf;
        l[j] = f[j] - hf;
    }
}
__device__ __forceinline__ uint4 pack8(const float* v) {
    return make_uint4(bf2pack(v[0], v[1]), bf2pack(v[2], v[3]),
                      bf2pack(v[4], v[5]), bf2pack(v[6], v[7]));
}
__device__ __forceinline__ uint32_t cvta_shared_u32(const void* p) {
    return (uint32_t)__cvta_generic_to_shared(p);
}
__device__ __forceinline__ void cpa16(uint32_t dst, const void* src, bool pred) {
    int sz = pred ? 16 : 0;
    asm volatile("cp.async.cg.shared.global [%0], [%1], 16, %2;"
                 :: "r"(dst), "l"(src), "r"(sz) : "memory");
}
#define CP_COMMIT() asm volatile("cp.async.commit_group;" ::: "memory")
#define CP_WAIT0()  asm volatile("cp.async.wait_group 0;" ::: "memory")

__device__ __forceinline__ void ldm_x4(uint32_t* r, uint32_t addr) {
    asm volatile("ldmatrix.sync.aligned.m8n8.x4.shared.b16 {%0,%1,%2,%3}, [%4];"
                 : "=r"(r[0]), "=r"(r[1]), "=r"(r[2]), "=r"(r[3]) : "r"(addr));
}
__device__ __forceinline__ void mma16816(float* c, const uint32_t* a,
                                         uint32_t b0, uint32_t b1) {
    asm volatile(
        "mma.sync.aligned.m16n8k16.row.col.f32.bf16.bf16.f32 "
        "{%0,%1,%2,%3}, {%4,%5,%6,%7}, {%8,%9}, {%0,%1,%2,%3};"
        : "+f"(c[0]), "+f"(c[1]), "+f"(c[2]), "+f"(c[3])
        : "r"(a[0]), "r"(a[1]), "r"(a[2]), "r"(a[3]), "r"(b0), "r"(b1));
}

// ---------------- small kernels ----------------
__global__ void zero_kernel(float* __restrict__ p, int n) {
    int i = blockIdx.x * blockDim.x + threadIdx.x;
    if (i < n) p[i] = 0.0f;
}

// elementwise split (emb -> embh/embl)
__global__ void esplit_kernel(const float* __restrict__ s, bf* __restrict__ h,
                              bf* __restrict__ l, int n) {
    int i = blockIdx.x * blockDim.x + threadIdx.x;
    if (i < n) { bf hb, lb; split1(s[i], hb, lb); h[i] = hb; l[i] = lb; }
}

// transpose + split: B [K][N] fp32 -> T [N][K] bf16 hi/lo
__global__ void tsplit_kernel(const float* __restrict__ B, bf* __restrict__ h,
                              bf* __restrict__ l, int K, int N) {
    int i = blockIdx.x * blockDim.x + threadIdx.x;
    if (i < K * N) {
        int k = i / N, n = i % N;
        bf hb, lb; split1(B[i], hb, lb);
        h[(size_t)n * K + k] = hb;
        l[(size_t)n * K + k] = lb;
    }
}

// node embedding: x fp32 + hi/lo planes
__global__ void node_embed_kernel(const int* __restrict__ ntok,
                                  const float* __restrict__ emb,
                                  float* __restrict__ x,
                                  bf* __restrict__ xh, bf* __restrict__ xl) {
    int i = blockIdx.x * blockDim.x + threadIdx.x;
    if (i < NN * FD) {
        int row = i >> 9;
        int col = i & 511;
        int l = col >> 6, d = col & 63;
        float v = emb[(size_t)ntok[row * LL + l] * DD + d];
        x[i] = v;
        bf hb, lb; split1(v, hb, lb);
        xh[i] = hb; xl[i] = lb;
    }
}

// edge masking + labels + masked embedding gather (hi/lo only)
__global__ void edge_mask_embed_kernel(const int* __restrict__ etok,
                                       const int* __restrict__ mask_rows,
                                       const float* __restrict__ emb,
                                       bf* __restrict__ eh, bf* __restrict__ el,
                                       float* __restrict__ labels_out) {
    int b = blockIdx.x;
    __shared__ int mt[LL];
    int t = threadIdx.x;
    if (t < LL) {
        int tok = etok[b * LL + t];
        bool special = ((unsigned)tok) < 4u;
        bool masked = (mask_rows[b] != 0) && !special;
        mt[t] = masked ? 4 : tok;
        if (labels_out) labels_out[b * LL + t] = masked ? (float)tok : -100.0f;
    }
    __syncthreads();
    for (int c = t; c < FD; c += blockDim.x) {
        int l = c >> 6, d = c & 63;
        float v = emb[(size_t)mt[l] * DD + d];
        bf hb, lb; split1(v, hb, lb);
        eh[(size_t)b * FD + c] = hb;
        el[(size_t)b * FD + c] = lb;
    }
}

__global__ void scatter_add_kernel(const float* __restrict__ msg,
                                   const int* __restrict__ dst,
                                   float* __restrict__ agg) {
    int i = blockIdx.x * blockDim.x + threadIdx.x;
    if (i < NE * FD) {
        int e = i >> 9;
        int n = i & 511;
        atomicAdd(&agg[(size_t)dst[e] * FD + n], msg[i]);
    }
}

// ================= pipelined bf16 HMMA GEMM: 128x128 tile, K chunks of 32 ====
// C = epi(A @ B^T_stored)  with A [M][K] bf16 hi/lo, B [N][K] bf16 hi/lo.
// 3-MMA hi/lo split: Ah*Bh + Ah*Bl + Al*Bh.
// AMODE 0: A = pre-split planes.  AMODE 1: A row m = Hf[idxa[e]]+Hf[idxb[e]] slice (fp32, split in-kernel).
// EPI: 0 none, 1 +bias[n], 2 relu(.+extra[m,n]), 3 relu(.+extra[idxa[m],n]),
//      4 .+extra[m,n], 5 gelu tanh
// WMODE bit0: write fp32 C; bit1: write bf16 hi/lo planes Ch/Cl.
#define PITCH 40                       // bf16 elems per smem row (80 B)
#define PLANE (128 * PITCH * 2)        // 10240 B
#define STG   (4 * PLANE)              // 40960 B per stage
#define GSMEM (2 * STG)                // 81920 B total

template <int AMODE, int EPI, int WMODE>
__global__ __launch_bounds__(256)
void gemm_bf(const bf* __restrict__ Ah, const bf* __restrict__ Al,
             const bf* __restrict__ Bh, const bf* __restrict__ Bl,
             float* __restrict__ C, bf* __restrict__ Ch, bf* __restrict__ Cl,
             int M, int N, int K,
             const float* __restrict__ bias, const float* __restrict__ extra,
             const int* __restrict__ idxa, const int* __restrict__ idxb,
             const float* __restrict__ Hf) {
    extern __shared__ __align__(16) char smem[];
    const uint32_t sm = cvta_shared_u32(smem);

    const int tid = threadIdx.x;
    const int lane = tid & 31;
    const int w = tid >> 5;
    const int m0 = blockIdx.y * 128;
    const int n0 = blockIdx.x * 128;
    const int wm = (w & 3) * 32;
    const int wn = (w >> 2) * 64;

    float c[2][8][4];
    #pragma unroll
    for (int mi = 0; mi < 2; mi++)
        #pragma unroll
        for (int nj = 0; nj < 8; nj++)
            #pragma unroll
            for (int q = 0; q < 4; q++) c[mi][nj][q] = 0.0f;

    const int nk = K >> 5;

    // ---- chunk loader ----
    auto load_chunk = [&](int kc, int s) {
        uint32_t sb = sm + s * STG;
        // A planes
        if (AMODE == 0) {
            #pragma unroll
            for (int i = 0; i < 2; i++) {
                int seg = tid + i * 256;          // 0..511
                int r = seg >> 2;
                int ko = (seg & 3) * 8;
                size_t go = (size_t)(m0 + r) * K + kc * 32 + ko;
                uint32_t ds = sb + (r * PITCH + ko) * 2;
                cpa16(ds,          Ah + go, true);
                cpa16(ds + PLANE,  Al + go, true);
            }
        } else {
            #pragma unroll
            for (int i = 0; i < 2; i++) {
                int seg = tid + i * 256;
                int r = seg >> 2;
                int ko = (seg & 3) * 8;
                int mg = m0 + r;
                int e = mg >> 3, l = mg & 7;
                const float4* pa = (const float4*)(Hf + (size_t)idxa[e] * FD + l * DD + kc * 32 + ko);
                const float4* pb = (const float4*)(Hf + (size_t)idxb[e] * FD + l * DD + kc * 32 + ko);
                float4 a0 = pa[0], a1 = pa[1], b0 = pb[0], b1 = pb[1];
                float f[8] = {a0.x+b0.x, a0.y+b0.y, a0.z+b0.z, a0.w+b0.w,
                              a1.x+b1.x, a1.y+b1.y, a1.z+b1.z, a1.w+b1.w};
                float h[8], l8[8];
                split8(f, h, l8);
                int off = s * STG + (r * PITCH + ko) * 2;
                *(uint4*)(smem + off) = pack8(h);
                *(uint4*)(smem + off + PLANE) = pack8(l8);
            }
        }
        // B planes [N][K]
        #pragma unroll
        for (int i = 0; i < 2; i++) {
            int seg = tid + i * 256;
            int r = seg >> 2;
            int ko = (seg & 3) * 8;
            bool valid = (n0 + r) < N;
            size_t go = valid ? ((size_t)(n0 + r) * K + kc * 32 + ko) : 0;
            uint32_t ds = sb + 2 * PLANE + (r * PITCH + ko) * 2;
            cpa16(ds,         Bh + go, valid);
            cpa16(ds + PLANE, Bl + go, valid);
        }
    };

    load_chunk(0, 0);
    CP_COMMIT();

    for (int kc = 0; kc < nk; kc++) {
        int s = kc & 1;
        CP_WAIT0();
        __syncthreads();
        if (kc + 1 < nk) load_chunk(kc + 1, s ^ 1);
        CP_COMMIT();

        uint32_t base = sm + s * STG;
        #pragma unroll
        for (int kk = 0; kk < 2; kk++) {
            const uint32_t ld_off = ((lane & 15) * PITCH + (lane >> 4) * 8 + kk * 16) * 2;
            uint32_t ah[2][4], al[2][4];
            #pragma unroll
            for (int mi = 0; mi < 2; mi++) {
                uint32_t rowoff = (wm + mi * 16) * (PITCH * 2);
                ldm_x4(ah[mi], base + rowoff + ld_off);
                ldm_x4(al[mi], base + PLANE + rowoff + ld_off);
            }
            uint32_t bh[4][4], bl[4][4];
            #pragma unroll
            for (int ni = 0; ni < 4; ni++) {
                uint32_t rowoff = (wn + ni * 16) * (PITCH * 2);
                ldm_x4(bh[ni], base + 2 * PLANE + rowoff + ld_off);
                ldm_x4(bl[ni], base + 3 * PLANE + rowoff + ld_off);
            }
            #pragma unroll
            for (int mi = 0; mi < 2; mi++) {
                #pragma unroll
                for (int nj = 0; nj < 8; nj++) {
                    int ni = nj >> 1, half = nj & 1;
                    uint32_t bh0 = bh[ni][half], bh1 = bh[ni][half + 2];
                    uint32_t bl0 = bl[ni][half], bl1 = bl[ni][half + 2];
                    mma16816(c[mi][nj], ah[mi], bh0, bh1);
                    mma16816(c[mi][nj], ah[mi], bl0, bl1);
                    mma16816(c[mi][nj], al[mi], bh0, bh1);
                }
            }
        }
    }

    // ---- epilogue ----
    const int gr = lane >> 2;
    const int gc = (lane & 3) * 2;
    #pragma unroll
    for (int mi = 0; mi < 2; mi++) {
        #pragma unroll
        for (int nj = 0; nj < 8; nj++) {
            int n = n0 + wn + nj * 8 + gc;
            if (n >= N) continue;
            #pragma unroll
            for (int half = 0; half < 2; half++) {
                int m = m0 + wm + mi * 16 + gr + half * 8;
                float v0 = c[mi][nj][half * 2 + 0];
                float v1 = c[mi][nj][half * 2 + 1];
                if (EPI == 1) { v0 += bias[n]; v1 += bias[n + 1]; }
                else if (EPI == 2) {
                    v0 += extra[(size_t)m * N + n];     v0 = fmaxf(v0, 0.0f);
                    v1 += extra[(size_t)m * N + n + 1]; v1 = fmaxf(v1, 0.0f);
                } else if (EPI == 3) {
                    size_t rb = (size_t)idxa[m] * N;
                    v0 += extra[rb + n];     v0 = fmaxf(v0, 0.0f);
                    v1 += extra[rb + n + 1]; v1 = fmaxf(v1, 0.0f);
                } else if (EPI == 4) {
                    v0 += extra[(size_t)m * N + n];
                    v1 += extra[(size_t)m * N + n + 1];
                } else if (EPI == 5) {
                    float c3 = v0 + 0.044715f * v0 * v0 * v0;
                    v0 = 0.5f * v0 * (1.0f + tanhf(0.7978845608028654f * c3));
                    c3 = v1 + 0.044715f * v1 * v1 * v1;
                    v1 = 0.5f * v1 * (1.0f + tanhf(0.7978845608028654f * c3));
                }
                if (WMODE & 1)
                    *(float2*)(C + (size_t)m * N + n) = make_float2(v0, v1);
                if (WMODE & 2) {
                    float h0 = __bfloat162float(__float2bfloat16_rn(v0));
                    float h1 = __bfloat162float(__float2bfloat16_rn(v1));
                    *(uint32_t*)(Ch + (size_t)m * N + n) = bf2pack(h0, h1);
                    *(uint32_t*)(Cl + (size_t)m * N + n) = bf2pack(v0 - h0, v1 - h1);
                }
            }
        }
    }
}

// ---------------- per-(edge,head) attention (QKV packed), writes bf16 hi/lo ---
__global__ void attn_kernel(const float* __restrict__ qkv,
                            bf* __restrict__ oh, bf* __restrict__ ol) {
    int b = blockIdx.x;
    int h = threadIdx.x >> 5;
    int lane = threadIdx.x & 31;
    int d0 = lane * 2;

    const size_t qbase = (size_t)b * LL * 768 + h * 64 + d0;
    float qr[LL][2], kr[LL][2], vr[LL][2];
    #pragma unroll
    for (int i = 0; i < LL; i++) {
        size_t ro = qbase + (size_t)i * 768;
        qr[i][0] = qkv[ro];           qr[i][1] = qkv[ro + 1];
        kr[i][0] = qkv[ro + 256];     kr[i][1] = qkv[ro + 257];
        vr[i][0] = qkv[ro + 512];     vr[i][1] = qkv[ro + 513];
    }

    float att[LL][LL];
    #pragma unroll
    for (int i = 0; i < LL; i++)
        #pragma unroll
        for (int j = 0; j < LL; j++) {
            float p = qr[i][0] * kr[j][0] + qr[i][1] * kr[j][1];
            #pragma unroll
            for (int off = 16; off > 0; off >>= 1)
                p += __shfl_xor_sync(0xffffffffu, p, off);
            att[i][j] = p * 0.125f;
        }

    #pragma unroll
    for (int i = 0; i < LL; i++) {
        float mx = att[i][0];
        #pragma unroll
        for (int j = 1; j < LL; j++) mx = fmaxf(mx, att[i][j]);
        float s = 0.0f;
        #pragma unroll
        for (int j = 0; j < LL; j++) { att[i][j] = expf(att[i][j] - mx); s += att[i][j]; }
        float inv = 1.0f / s;
        float o0 = 0.0f, o1 = 0.0f;
        #pragma unroll
        for (int j = 0; j < LL; j++) {
            float a = att[i][j] * inv;
            o0 = fmaf(a, vr[j][0], o0);
            o1 = fmaf(a, vr[j][1], o1);
        }
        size_t oi = (size_t)b * LL * DG + (size_t)i * DG + h * 64 + d0;
        float h0 = __bfloat162float(__float2bfloat16_rn(o0));
        float h1 = __bfloat162float(__float2bfloat16_rn(o1));
        *(uint32_t*)(oh + oi) = bf2pack(h0, h1);
        *(uint32_t*)(ol + oi) = bf2pack(o0 - h0, o1 - h1);
    }
}

// ---------------- final softmax over V per row (float4 vectorized) ----------------
#define NF4 2500   // VV/4

__global__ __launch_bounds__(256)
void lm_softmax_kernel(const float* __restrict__ logits, float* __restrict__ probs) {
    int r = blockIdx.x;
    int t = threadIdx.x;
    const float4* row = (const float4*)(logits + (size_t)r * VV);
    float4* orow = (float4*)(probs + (size_t)r * VV);

    float4 vals[10];
    float mx = -INFINITY;
    #pragma unroll
    for (int i = 0; i < 10; i++) {
        int c = t + i * 256;
        if (c < NF4) {
            float4 v = row[c];
            vals[i] = v;
            mx = fmaxf(mx, fmaxf(fmaxf(v.x, v.y), fmaxf(v.z, v.w)));
        }
    }
    __shared__ float sred[8];
    #pragma unroll
    for (int off = 16; off > 0; off >>= 1) mx = fmaxf(mx, __shfl_xor_sync(0xffffffffu, mx, off));
    if ((t & 31) == 0) sred[t >> 5] = mx;
    __syncthreads();
    if (t < 32) {
        float v2 = (t < 8) ? sred[t] : -INFINITY;
        #pragma unroll
        for (int off = 4; off > 0; off >>= 1) v2 = fmaxf(v2, __shfl_xor_sync(0xffffffffu, v2, off));
        if (t == 0) sred[0] = v2;
    }
    __syncthreads();
    mx = sred[0];
    __syncthreads();

    float s = 0.0f;
    #pragma unroll
    for (int i = 0; i < 10; i++) {
        int c = t + i * 256;
        if (c < NF4) {
            float4 v = vals[i];
            v.x = __expf(v.x - mx); v.y = __expf(v.y - mx);
            v.z = __expf(v.z - mx); v.w = __expf(v.w - mx);
            vals[i] = v;
            s += v.x + v.y + v.z + v.w;
        }
    }
    #pragma unroll
    for (int off = 16; off > 0; off >>= 1) s += __shfl_xor_sync(0xffffffffu, s, off);
    if ((t & 31) == 0) sred[t >> 5] = s;
    __syncthreads();
    if (t < 32) {
        float v2 = (t < 8) ? sred[t] : 0.0f;
        #pragma unroll
        for (int off = 4; off > 0; off >>= 1) v2 += __shfl_xor_sync(0xffffffffu, v2, off);
        if (t == 0) sred[0] = v2;
    }
    __syncthreads();
    float inv = 1.0f / sred[0];

    #pragma unroll
    for (int i = 0; i < 10; i++) {
        int c = t + i * 256;
        if (c < NF4) {
            float4 v = vals[i];
            v.x *= inv; v.y *= inv; v.z *= inv; v.w *= inv;
            orow[c] = v;
        }
    }
}

// ---------------- host launch ----------------
#define SYM(var, sym) void* var##_v; cudaGetSymbolAddress(&var##_v, sym);

extern "C" void kernel_launch(void* const* d_in, const int* in_sizes, int n_in,
                              void* d_out, int out_size) {
    const int* node_tokens = (const int*)d_in[0];
    const int* edge_tokens = (const int*)d_in[1];
    const int* edge_index  = (const int*)d_in[2];
    const int* mask_rows   = (const int*)d_in[3];
    const float* emb    = (const float*)d_in[4];
    const float* W_msg  = (const float*)d_in[5];
    const float* W_node = (const float*)d_in[6];
    const float* lc1_w  = (const float*)d_in[7];
    const float* lc1_b  = (const float*)d_in[8];
    const float* lc2_w  = (const float*)d_in[9];
    const float* lc2_b  = (const float*)d_in[10];
    const float* Wq  = (const float*)d_in[11];
    const float* Wk  = (const float*)d_in[12];
    const float* Wv  = (const float*)d_in[13];
    const float* Wo  = (const float*)d_in[14];
    const float* Wf1 = (const float*)d_in[15];
    const float* Wf2 = (const float*)d_in[16];

    const int* src = edge_index;
    const int* dst = edge_index + NE;

    float* out = (float*)d_out;
    float* labels_ptr = nullptr;
    float* probs_ptr  = nullptr;
    long total = (long)NTOK * VV;
    if ((long)out_size >= total + NTOK) { labels_ptr = out; probs_ptr = out + NTOK; }
    else if ((long)out_size >= total)   { probs_ptr = out; }
    else                                { labels_ptr = out; }

    SYM(X, g_x)   SYM(MSG, g_msg) SYM(AGG, g_agg) SYM(H, g_h)
    SYM(Z, g_z)   SYM(QKV, g_qkv) SYM(X1, g_x1)   SYM(LOG, g_logits)
    SYM(Xh, g_Xh) SYM(Xl, g_Xl)   SYM(Eh, g_Eh)   SYM(El, g_El)
    SYM(Zh, g_Zh) SYM(Zl, g_Zl)   SYM(ATh, g_ATh) SYM(ATl, g_ATl)
    SYM(X1h, g_X1h) SYM(X1l, g_X1l) SYM(FFh, g_FFh) SYM(FFl, g_FFl)
    SYM(X2h, g_X2h) SYM(X2l, g_X2l) SYM(Yh, g_Yh)   SYM(Yl, g_Yl)
    SYM(embh, g_embh) SYM(embl, g_embl)
    SYM(WmsgTh, g_WmsgTh) SYM(WmsgTl, g_WmsgTl)
    SYM(WnodeTh, g_WnodeTh) SYM(WnodeTl, g_WnodeTl)
    SYM(lc1Th, g_lc1Th) SYM(lc1Tl, g_lc1Tl)
    SYM(qkvTh, g_qkvTh) SYM(qkvTl, g_qkvTl)
    SYM(WoTh, g_WoTh) SYM(WoTl, g_WoTl)
    SYM(Wf1Th, g_Wf1Th) SYM(Wf1Tl, g_Wf1Tl)
    SYM(Wf2Th, g_Wf2Th) SYM(Wf2Tl, g_Wf2Tl)
    SYM(lc2Th, g_lc2Th) SYM(lc2Tl, g_lc2Tl)

    // raise dynamic smem limits (idempotent)
    cudaFuncSetAttribute(gemm_bf<0,3,1>, cudaFuncAttributeMaxDynamicSharedMemorySize, GSMEM);
    cudaFuncSetAttribute(gemm_bf<0,2,1>, cudaFuncAttributeMaxDynamicSharedMemorySize, GSMEM);
    cudaFuncSetAttribute(gemm_bf<1,1,3>, cudaFuncAttributeMaxDynamicSharedMemorySize, GSMEM);
    cudaFuncSetAttribute(gemm_bf<0,0,1>, cudaFuncAttributeMaxDynamicSharedMemorySize, GSMEM);
    cudaFuncSetAttribute(gemm_bf<0,4,3>, cudaFuncAttributeMaxDynamicSharedMemorySize, GSMEM);
    cudaFuncSetAttribute(gemm_bf<0,5,2>, cudaFuncAttributeMaxDynamicSharedMemorySize, GSMEM);
    cudaFuncSetAttribute(gemm_bf<0,4,2>, cudaFuncAttributeMaxDynamicSharedMemorySize, GSMEM);
    cudaFuncSetAttribute(gemm_bf<0,1,2>, cudaFuncAttributeMaxDynamicSharedMemorySize, GSMEM);

    // 0. weight pre-split (transposed to [N][K]) + emb split
    tsplit_kernel<<<(FD*FD+255)/256, 256>>>(W_msg,  (bf*)WmsgTh_v,  (bf*)WmsgTl_v,  FD, FD);
    tsplit_kernel<<<(FD*FD+255)/256, 256>>>(W_node, (bf*)WnodeTh_v, (bf*)WnodeTl_v, FD, FD);
    tsplit_kernel<<<(DD*DG+255)/256, 256>>>(lc1_w,  (bf*)lc1Th_v,   (bf*)lc1Tl_v,   DD, DG);
    tsplit_kernel<<<(DG*DG+255)/256, 256>>>(Wq, (bf*)qkvTh_v,            (bf*)qkvTl_v,            DG, DG);
    tsplit_kernel<<<(DG*DG+255)/256, 256>>>(Wk, (bf*)qkvTh_v + DG*DG,    (bf*)qkvTl_v + DG*DG,    DG, DG);
    tsplit_kernel<<<(DG*DG+255)/256, 256>>>(Wv, (bf*)qkvTh_v + 2*DG*DG,  (bf*)qkvTl_v + 2*DG*DG,  DG, DG);
    tsplit_kernel<<<(DG*DG+255)/256, 256>>>(Wo,  (bf*)WoTh_v,  (bf*)WoTl_v,  DG, DG);
    tsplit_kernel<<<(DG*4*DG+255)/256, 256>>>(Wf1, (bf*)Wf1Th_v, (bf*)Wf1Tl_v, DG, 4*DG);
    tsplit_kernel<<<(4*DG*DG+255)/256, 256>>>(Wf2, (bf*)Wf2Th_v, (bf*)Wf2Tl_v, 4*DG, DG);
    tsplit_kernel<<<(DG*DD+255)/256, 256>>>(lc2_w, (bf*)lc2Th_v, (bf*)lc2Tl_v, DG, DD);
    esplit_kernel<<<(VV*DD+255)/256, 256>>>(emb, (bf*)embh_v, (bf*)embl_v, VV*DD);

    // 1. embeddings
    node_embed_kernel<<<(NN*FD+255)/256, 256>>>(node_tokens, emb, (float*)X_v, (bf*)Xh_v, (bf*)Xl_v);
    edge_mask_embed_kernel<<<NE, 256>>>(edge_tokens, mask_rows, emb, (bf*)Eh_v, (bf*)El_v, labels_ptr);

    if (probs_ptr == nullptr) return;

    zero_kernel<<<(NN*FD+255)/256, 256>>>((float*)AGG_v, NN*FD);
    // 2. msg = relu(e @ W_msg + x[src])
    gemm_bf<0,3,1><<<dim3(4,16), 256, GSMEM>>>((bf*)Eh_v, (bf*)El_v, (bf*)WmsgTh_v, (bf*)WmsgTl_v,
        (float*)MSG_v, nullptr, nullptr, NE, FD, FD, nullptr, (float*)X_v, src, nullptr, nullptr);
    // 3. agg = segment_sum(msg, dst)
    scatter_add_kernel<<<(NE*FD+255)/256, 256>>>((float*)MSG_v, dst, (float*)AGG_v);
    // 4. h = relu(x @ W_node + agg)
    gemm_bf<0,2,1><<<dim3(4,64), 256, GSMEM>>>((bf*)Xh_v, (bf*)Xl_v, (bf*)WnodeTh_v, (bf*)WnodeTl_v,
        (float*)H_v, nullptr, nullptr, NN, FD, FD, nullptr, (float*)AGG_v, nullptr, nullptr, nullptr);
    // 5. z = (h[src]+h[dst]) @ lc1_w + lc1_b
    gemm_bf<1,1,3><<<dim3(2,128), 256, GSMEM>>>(nullptr, nullptr, (bf*)lc1Th_v, (bf*)lc1Tl_v,
        (float*)Z_v, (bf*)Zh_v, (bf*)Zl_v, NTOK, DG, DD, lc1_b, nullptr, src, dst, (float*)H_v);
    // 6. qkv = z @ [Wq|Wk|Wv]
    gemm_bf<0,0,1><<<dim3(6,128), 256, GSMEM>>>((bf*)Zh_v, (bf*)Zl_v, (bf*)qkvTh_v, (bf*)qkvTl_v,
        (float*)QKV_v, nullptr, nullptr, NTOK, 3*DG, DG, nullptr, nullptr, nullptr, nullptr, nullptr);
    // 7. attention
    attn_kernel<<<NE, 128>>>((float*)QKV_v, (bf*)ATh_v, (bf*)ATl_v);
    // 8. x1 = z + attn @ Wo
    gemm_bf<0,4,3><<<dim3(2,128), 256, GSMEM>>>((bf*)ATh_v, (bf*)ATl_v, (bf*)WoTh_v, (bf*)WoTl_v,
        (float*)X1_v, (bf*)X1h_v, (bf*)X1l_v, NTOK, DG, DG, nullptr, (float*)Z_v, nullptr, nullptr, nullptr);
    // 9. ffn = gelu(x1 @ Wf1)
    gemm_bf<0,5,2><<<dim3(8,128), 256, GSMEM>>>((bf*)X1h_v, (bf*)X1l_v, (bf*)Wf1Th_v, (bf*)Wf1Tl_v,
        nullptr, (bf*)FFh_v, (bf*)FFl_v, NTOK, 4*DG, DG, nullptr, nullptr, nullptr, nullptr, nullptr);
    // 10. x2 = x1 + ffn @ Wf2
    gemm_bf<0,4,2><<<dim3(2,128), 256, GSMEM>>>((bf*)FFh_v, (bf*)FFl_v, (bf*)Wf2Th_v, (bf*)Wf2Tl_v,
        nullptr, (bf*)X2h_v, (bf*)X2l_v, NTOK, DG, 4*DG, nullptr, (float*)X1_v, nullptr, nullptr, nullptr);
    // 11. y = x2 @ lc2_w + lc2_b
    gemm_bf<0,1,2><<<dim3(1,128), 256, GSMEM>>>((bf*)X2h_v, (bf*)X2l_v, (bf*)lc2Th_v, (bf*)lc2Tl_v,
        nullptr, (bf*)Yh_v, (bf*)Yl_v, NTOK, DD, DG, lc2_b, nullptr, nullptr, nullptr, nullptr);
    // 12. logits = y @ emb.T
    gemm_bf<0,0,1><<<dim3((VV+127)/128,128), 256, GSMEM>>>((bf*)Yh_v, (bf*)Yl_v, (bf*)embh_v, (bf*)embl_v,
        (float*)LOG_v, nullptr, nullptr, NTOK, VV, DD, nullptr, nullptr, nullptr, nullptr, nullptr);
    // 13. probs = softmax(logits)
    lm_softmax_kernel<<<NTOK, 256>>>((float*)LOG_v, probs_ptr);
}

// round 11
// speedup vs baseline: 2.1480x; 1.1010x over previous
#include <cuda_runtime.h>
#include <cuda_bf16.h>
#include <math.h>
#include <stdint.h>

// Problem constants
#define NN 8192      // nodes
#define NE 2048      // edges
#define LL 8         // tokens per node/edge
#define DD 64        // gnn hidden
#define FD 512       // LL*DD
#define DG 256       // gpt hidden
#define VV 10000     // vocab
#define NTOK 16384   // NE*LL
#define NTILE 79     // ceil(VV/128)

typedef __nv_bfloat16 bf;

// ---------------- fp32 scratch ----------------
__device__ float g_x[NN * FD];
__device__ float g_msg[NE * FD];
__device__ float g_agg[NN * FD];
__device__ float g_h[NN * FD];
__device__ float g_z[NTOK * DG];
__device__ float g_qkv[NTOK * 3 * DG];
__device__ float g_x1[NTOK * DG];
__device__ float2 g_stats[(size_t)NTOK * 80];   // per-(row,tile) (max, sumexp)
__device__ float2 g_rowstat[NTOK];              // per-row (max, 1/sum)

// ---------------- bf16 hi/lo planes ----------------
__device__ bf g_Xh[NN * FD],  g_Xl[NN * FD];
__device__ bf g_Eh[NE * FD],  g_El[NE * FD];
__device__ bf g_Zh[NTOK * DG], g_Zl[NTOK * DG];
__device__ bf g_ATh[NTOK * DG], g_ATl[NTOK * DG];
__device__ bf g_X1h[NTOK * DG], g_X1l[NTOK * DG];
__device__ bf g_FFh[NTOK * 4 * DG], g_FFl[NTOK * 4 * DG];
__device__ bf g_X2h[NTOK * DG], g_X2l[NTOK * DG];
__device__ bf g_Yh[NTOK * DD], g_Yl[NTOK * DD];
__device__ bf g_embh[VV * DD], g_embl[VV * DD];
// transposed weights [N][K]
__device__ bf g_WmsgTh[FD * FD],  g_WmsgTl[FD * FD];
__device__ bf g_WnodeTh[FD * FD], g_WnodeTl[FD * FD];
__device__ bf g_lc1Th[DG * DD],   g_lc1Tl[DG * DD];
__device__ bf g_qkvTh[3 * DG * DG], g_qkvTl[3 * DG * DG];
__device__ bf g_WoTh[DG * DG],    g_WoTl[DG * DG];
__device__ bf g_Wf1Th[4 * DG * DG], g_Wf1Tl[4 * DG * DG];
__device__ bf g_Wf2Th[DG * 4 * DG], g_Wf2Tl[DG * 4 * DG];
__device__ bf g_lc2Th[DD * DG],   g_lc2Tl[DD * DG];

// ---------------- helpers ----------------
__device__ __forceinline__ uint32_t bf2pack(float x0, float x1) {
    __nv_bfloat162 h = __floats2bfloat162_rn(x0, x1);
    return *(uint32_t*)&h;
}
__device__ __forceinline__ void split1(float v, bf& h, bf& l) {
    h = __float2bfloat16_rn(v);
    l = __float2bfloat16_rn(v - __bfloat162float(h));
}
__device__ __forceinline__ void split8(const float* f, float* h, float* l) {
    #pragma unroll
    for (int j = 0; j < 8; j++) {
        float hf = __bfloat162float(__float2bfloat16_rn(f[j]));
        h[j] = hf;
        l[j] = f[j] - hf;
    }
}
__device__ __forceinline__ uint4 pack8(const float* v) {
    return make_uint4(bf2pack(v[0], v[1]), bf2pack(v[2], v[3]),
                      bf2pack(v[4], v[5]), bf2pack(v[6], v[7]));
}
__device__ __forceinline__ uint32_t cvta_shared_u32(const void* p) {
    return (uint32_t)__cvta_generic_to_shared(p);
}
__device__ __forceinline__ void cpa16(uint32_t dst, const void* src, bool pred) {
    int sz = pred ? 16 : 0;
    asm volatile("cp.async.cg.shared.global [%0], [%1], 16, %2;"
                 :: "r"(dst), "l"(src), "r"(sz) : "memory");
}
#define CP_COMMIT() asm volatile("cp.async.commit_group;" ::: "memory")
#define CP_WAIT0()  asm volatile("cp.async.wait_group 0;" ::: "memory")

__device__ __forceinline__ void ldm_x4(uint32_t* r, uint32_t addr) {
    asm volatile("ldmatrix.sync.aligned.m8n8.x4.shared.b16 {%0,%1,%2,%3}, [%4];"
                 : "=r"(r[0]), "=r"(r[1]), "=r"(r[2]), "=r"(r[3]) : "r"(addr));
}
__device__ __forceinline__ void mma16816(float* c, const uint32_t* a,
                                         uint32_t b0, uint32_t b1) {
    asm volatile(
        "mma.sync.aligned.m16n8k16.row.col.f32.bf16.bf16.f32 "
        "{%0,%1,%2,%3}, {%4,%5,%6,%7}, {%8,%9}, {%0,%1,%2,%3};"
        : "+f"(c[0]), "+f"(c[1]), "+f"(c[2]), "+f"(c[3])
        : "r"(a[0]), "r"(a[1]), "r"(a[2]), "r"(a[3]), "r"(b0), "r"(b1));
}

// ---------------- small kernels ----------------
__global__ void zero_kernel(float* __restrict__ p, int n) {
    int i = blockIdx.x * blockDim.x + threadIdx.x;
    if (i < n) p[i] = 0.0f;
}

// one fused kernel for ALL weight transposes/splits + emb split
#define NJOBS 11
struct SJobs {
    const float* src[NJOBS];
    bf* h[NJOBS];
    bf* l[NJOBS];
    int N[NJOBS];     // source inner dim (transpose); 1 => identity copy
    int K[NJOBS];     // source outer dim (dst stride)
    int end[NJOBS];   // exclusive prefix sum of counts
};
__global__ void split_all_kernel(SJobs jb, int total) {
    int i = blockIdx.x * blockDim.x + threadIdx.x;
    if (i >= total) return;
    int j = 0;
    while (i >= jb.end[j]) j++;
    int base = (j == 0) ? 0 : jb.end[j - 1];
    int local = i - base;
    int N = jb.N[j];
    int k = local / N;
    int n = local - k * N;
    bf hb, lb; split1(jb.src[j][local], hb, lb);
    size_t di = (size_t)n * jb.K[j] + k;
    jb.h[j][di] = hb;
    jb.l[j][di] = lb;
}

// node embedding: x fp32 + hi/lo planes
__global__ void node_embed_kernel(const int* __restrict__ ntok,
                                  const float* __restrict__ emb,
                                  float* __restrict__ x,
                                  bf* __restrict__ xh, bf* __restrict__ xl) {
    int i = blockIdx.x * blockDim.x + threadIdx.x;
    if (i < NN * FD) {
        int row = i >> 9;
        int col = i & 511;
        int l = col >> 6, d = col & 63;
        float v = emb[(size_t)ntok[row * LL + l] * DD + d];
        x[i] = v;
        bf hb, lb; split1(v, hb, lb);
        xh[i] = hb; xl[i] = lb;
    }
}

// edge masking + labels + masked embedding gather (hi/lo only)
__global__ void edge_mask_embed_kernel(const int* __restrict__ etok,
                                       const int* __restrict__ mask_rows,
                                       const float* __restrict__ emb,
                                       bf* __restrict__ eh, bf* __restrict__ el,
                                       float* __restrict__ labels_out) {
    int b = blockIdx.x;
    __shared__ int mt[LL];
    int t = threadIdx.x;
    if (t < LL) {
        int tok = etok[b * LL + t];
        bool special = ((unsigned)tok) < 4u;
        bool masked = (mask_rows[b] != 0) && !special;
        mt[t] = masked ? 4 : tok;
        if (labels_out) labels_out[b * LL + t] = masked ? (float)tok : -100.0f;
    }
    __syncthreads();
    for (int c = t; c < FD; c += blockDim.x) {
        int l = c >> 6, d = c & 63;
        float v = emb[(size_t)mt[l] * DD + d];
        bf hb, lb; split1(v, hb, lb);
        eh[(size_t)b * FD + c] = hb;
        el[(size_t)b * FD + c] = lb;
    }
}

__global__ void scatter_add_kernel(const float* __restrict__ msg,
                                   const int* __restrict__ dst,
                                   float* __restrict__ agg) {
    int i = blockIdx.x * blockDim.x + threadIdx.x;
    if (i < NE * FD) {
        int e = i >> 9;
        int n = i & 511;
        atomicAdd(&agg[(size_t)dst[e] * FD + n], msg[i]);
    }
}

// ================= pipelined bf16 HMMA GEMM: 128x128 tile, K chunks of 32 ====
#define PITCH 40                       // bf16 elems per smem row (80 B)
#define PLANE (128 * PITCH * 2)        // 10240 B
#define STG   (4 * PLANE)              // 40960 B per stage
#define GSMEM (2 * STG)                // 81920 B total

template <int AMODE, int EPI, int WMODE>
__global__ __launch_bounds__(256)
void gemm_bf(const bf* __restrict__ Ah, const bf* __restrict__ Al,
             const bf* __restrict__ Bh, const bf* __restrict__ Bl,
             float* __restrict__ C, bf* __restrict__ Ch, bf* __restrict__ Cl,
             int M, int N, int K,
             const float* __restrict__ bias, const float* __restrict__ extra,
             const int* __restrict__ idxa, const int* __restrict__ idxb,
             const float* __restrict__ Hf) {
    extern __shared__ __align__(16) char smem[];
    const uint32_t sm = cvta_shared_u32(smem);

    const int tid = threadIdx.x;
    const int lane = tid & 31;
    const int w = tid >> 5;
    const int m0 = blockIdx.y * 128;
    const int n0 = blockIdx.x * 128;
    const int wm = (w & 3) * 32;
    const int wn = (w >> 2) * 64;

    float c[2][8][4];
    #pragma unroll
    for (int mi = 0; mi < 2; mi++)
        #pragma unroll
        for (int nj = 0; nj < 8; nj++)
            #pragma unroll
            for (int q = 0; q < 4; q++) c[mi][nj][q] = 0.0f;

    const int nk = K >> 5;

    auto load_chunk = [&](int kc, int s) {
        uint32_t sb = sm + s * STG;
        if (AMODE == 0) {
            #pragma unroll
            for (int i = 0; i < 2; i++) {
                int seg = tid + i * 256;
                int r = seg >> 2;
                int ko = (seg & 3) * 8;
                size_t go = (size_t)(m0 + r) * K + kc * 32 + ko;
                uint32_t ds = sb + (r * PITCH + ko) * 2;
                cpa16(ds,          Ah + go, true);
                cpa16(ds + PLANE,  Al + go, true);
            }
        } else {
            #pragma unroll
            for (int i = 0; i < 2; i++) {
                int seg = tid + i * 256;
                int r = seg >> 2;
                int ko = (seg & 3) * 8;
                int mg = m0 + r;
                int e = mg >> 3, l = mg & 7;
                const float4* pa = (const float4*)(Hf + (size_t)idxa[e] * FD + l * DD + kc * 32 + ko);
                const float4* pb = (const float4*)(Hf + (size_t)idxb[e] * FD + l * DD + kc * 32 + ko);
                float4 a0 = pa[0], a1 = pa[1], b0 = pb[0], b1 = pb[1];
                float f[8] = {a0.x+b0.x, a0.y+b0.y, a0.z+b0.z, a0.w+b0.w,
                              a1.x+b1.x, a1.y+b1.y, a1.z+b1.z, a1.w+b1.w};
                float h[8], l8[8];
                split8(f, h, l8);
                int off = s * STG + (r * PITCH + ko) * 2;
                *(uint4*)(smem + off) = pack8(h);
                *(uint4*)(smem + off + PLANE) = pack8(l8);
            }
        }
        #pragma unroll
        for (int i = 0; i < 2; i++) {
            int seg = tid + i * 256;
            int r = seg >> 2;
            int ko = (seg & 3) * 8;
            bool valid = (n0 + r) < N;
            size_t go = valid ? ((size_t)(n0 + r) * K + kc * 32 + ko) : 0;
            uint32_t ds = sb + 2 * PLANE + (r * PITCH + ko) * 2;
            cpa16(ds,         Bh + go, valid);
            cpa16(ds + PLANE, Bl + go, valid);
        }
    };

    load_chunk(0, 0);
    CP_COMMIT();

    for (int kc = 0; kc < nk; kc++) {
        int s = kc & 1;
        CP_WAIT0();
        __syncthreads();
        if (kc + 1 < nk) load_chunk(kc + 1, s ^ 1);
        CP_COMMIT();

        uint32_t base = sm + s * STG;
        #pragma unroll
        for (int kk = 0; kk < 2; kk++) {
            const uint32_t ld_off = ((lane & 15) * PITCH + (lane >> 4) * 8 + kk * 16) * 2;
            uint32_t ah[2][4], al[2][4];
            #pragma unroll
            for (int mi = 0; mi < 2; mi++) {
                uint32_t rowoff = (wm + mi * 16) * (PITCH * 2);
                ldm_x4(ah[mi], base + rowoff + ld_off);
                ldm_x4(al[mi], base + PLANE + rowoff + ld_off);
            }
            uint32_t bh[4][4], bl[4][4];
            #pragma unroll
            for (int ni = 0; ni < 4; ni++) {
                uint32_t rowoff = (wn + ni * 16) * (PITCH * 2);
                ldm_x4(bh[ni], base + 2 * PLANE + rowoff + ld_off);
                ldm_x4(bl[ni], base + 3 * PLANE + rowoff + ld_off);
            }
            #pragma unroll
            for (int mi = 0; mi < 2; mi++) {
                #pragma unroll
                for (int nj = 0; nj < 8; nj++) {
                    int ni = nj >> 1, half = nj & 1;
                    uint32_t bh0 = bh[ni][half], bh1 = bh[ni][half + 2];
                    uint32_t bl0 = bl[ni][half], bl1 = bl[ni][half + 2];
                    mma16816(c[mi][nj], ah[mi], bh0, bh1);
                    mma16816(c[mi][nj], ah[mi], bl0, bl1);
                    mma16816(c[mi][nj], al[mi], bh0, bh1);
                }
            }
        }
    }

    const int gr = lane >> 2;
    const int gc = (lane & 3) * 2;
    #pragma unroll
    for (int mi = 0; mi < 2; mi++) {
        #pragma unroll
        for (int nj = 0; nj < 8; nj++) {
            int n = n0 + wn + nj * 8 + gc;
            if (n >= N) continue;
            #pragma unroll
            for (int half = 0; half < 2; half++) {
                int m = m0 + wm + mi * 16 + gr + half * 8;
                float v0 = c[mi][nj][half * 2 + 0];
                float v1 = c[mi][nj][half * 2 + 1];
                if (EPI == 1) { v0 += bias[n]; v1 += bias[n + 1]; }
                else if (EPI == 2) {
                    v0 += extra[(size_t)m * N + n];     v0 = fmaxf(v0, 0.0f);
                    v1 += extra[(size_t)m * N + n + 1]; v1 = fmaxf(v1, 0.0f);
                } else if (EPI == 3) {
                    size_t rb = (size_t)idxa[m] * N;
                    v0 += extra[rb + n];     v0 = fmaxf(v0, 0.0f);
                    v1 += extra[rb + n + 1]; v1 = fmaxf(v1, 0.0f);
                } else if (EPI == 4) {
                    v0 += extra[(size_t)m * N + n];
                    v1 += extra[(size_t)m * N + n + 1];
                } else if (EPI == 5) {
                    float c3 = v0 + 0.044715f * v0 * v0 * v0;
                    v0 = 0.5f * v0 * (1.0f + tanhf(0.7978845608028654f * c3));
                    c3 = v1 + 0.044715f * v1 * v1 * v1;
                    v1 = 0.5f * v1 * (1.0f + tanhf(0.7978845608028654f * c3));
                }
                if (WMODE & 1)
                    *(float2*)(C + (size_t)m * N + n) = make_float2(v0, v1);
                if (WMODE & 2) {
                    float h0 = __bfloat162float(__float2bfloat16_rn(v0));
                    float h1 = __bfloat162float(__float2bfloat16_rn(v1));
                    *(uint32_t*)(Ch + (size_t)m * N + n) = bf2pack(h0, h1);
                    *(uint32_t*)(Cl + (size_t)m * N + n) = bf2pack(v0 - h0, v1 - h1);
                }
            }
        }
    }
}

// ================= fused LM head: K=64 GEMM, two passes =======================
// PASS 0: per-(row, n-tile) (max, sumexp) -> stats.  PASS 1: probs written directly.
#define LMPITCH 72
#define LMPLANE (128 * LMPITCH * 2)    // 18432 B
#define LMSMEM  (4 * LMPLANE)          // 73728 B

template <int PASS>
__global__ __launch_bounds__(256)
void lm_gemm(const bf* __restrict__ Yh, const bf* __restrict__ Yl,
             const bf* __restrict__ Ebh, const bf* __restrict__ Ebl,
             float2* __restrict__ stats, const float2* __restrict__ rowstat,
             float* __restrict__ probs) {
    extern __shared__ __align__(16) char smem[];
    __shared__ float2 sstat[128];
    const uint32_t sm = cvta_shared_u32(smem);

    const int tid = threadIdx.x;
    const int lane = tid & 31;
    const int w = tid >> 5;
    const int m0 = blockIdx.y * 128;
    const int n0 = blockIdx.x * 128;
    const int wm = (w & 3) * 32;
    const int wn = (w >> 2) * 64;

    // one-shot load: A (Y) planes 0,1; B (emb) planes 2,3. 128 rows x 64 k each.
    #pragma unroll
    for (int i = 0; i < 4; i++) {
        int seg = tid + i * 256;       // 0..1023
        int r = seg >> 3;
        int ko = (seg & 7) * 8;
        uint32_t ds = sm + (r * LMPITCH + ko) * 2;
        size_t ga = (size_t)(m0 + r) * DD + ko;
        cpa16(ds,           Yh + ga, true);
        cpa16(ds + LMPLANE, Yl + ga, true);
        bool valid = (n0 + r) < VV;
        size_t gb = valid ? ((size_t)(n0 + r) * DD + ko) : 0;
        cpa16(ds + 2 * LMPLANE, Ebh + gb, valid);
        cpa16(ds + 3 * LMPLANE, Ebl + gb, valid);
    }
    CP_COMMIT();
    CP_WAIT0();
    __syncthreads();

    float c[2][8][4];
    #pragma unroll
    for (int mi = 0; mi < 2; mi++)
        #pragma unroll
        for (int nj = 0; nj < 8; nj++)
            #pragma unroll
            for (int q = 0; q < 4; q++) c[mi][nj][q] = 0.0f;

    #pragma unroll
    for (int kk = 0; kk < 4; kk++) {
        const uint32_t ld_off = ((lane & 15) * LMPITCH + (lane >> 4) * 8 + kk * 16) * 2;
        uint32_t ah[2][4], al[2][4];
        #pragma unroll
        for (int mi = 0; mi < 2; mi++) {
            uint32_t rowoff = (wm + mi * 16) * (LMPITCH * 2);
            ldm_x4(ah[mi], sm + rowoff + ld_off);
            ldm_x4(al[mi], sm + LMPLANE + rowoff + ld_off);
        }
        uint32_t bh[4][4], bl[4][4];
        #pragma unroll
        for (int ni = 0; ni < 4; ni++) {
            uint32_t rowoff = (wn + ni * 16) * (LMPITCH * 2);
            ldm_x4(bh[ni], sm + 2 * LMPLANE + rowoff + ld_off);
            ldm_x4(bl[ni], sm + 3 * LMPLANE + rowoff + ld_off);
        }
        #pragma unroll
        for (int mi = 0; mi < 2; mi++) {
            #pragma unroll
            for (int nj = 0; nj < 8; nj++) {
                int ni = nj >> 1, half = nj & 1;
                uint32_t b0 = bh[ni][half], b1 = bh[ni][half + 2];
                uint32_t c0 = bl[ni][half], c1 = bl[ni][half + 2];
                mma16816(c[mi][nj], ah[mi], b0, b1);
                mma16816(c[mi][nj], ah[mi], c0, c1);
                mma16816(c[mi][nj], al[mi], b0, b1);
            }
        }
    }

    const int gr = lane >> 2;
    const int gc = (lane & 3) * 2;

    if (PASS == 0) {
        float rqm[4], rqs[4];
        int idx = 0;
        #pragma unroll
        for (int mi = 0; mi < 2; mi++) {
            #pragma unroll
            for (int half = 0; half < 2; half++) {
                float vals[16];
                float vmax = -1e30f;
                int vi = 0;
                #pragma unroll
                for (int nj = 0; nj < 8; nj++) {
                    #pragma unroll
                    for (int q = 0; q < 2; q++) {
                        int n = n0 + wn + nj * 8 + gc + q;
                        float v = (n < VV) ? c[mi][nj][half * 2 + q] : -1e30f;
                        vals[vi++] = v;
                        vmax = fmaxf(vmax, v);
                    }
                }
                vmax = fmaxf(vmax, __shfl_xor_sync(0xffffffffu, vmax, 1));
                vmax = fmaxf(vmax, __shfl_xor_sync(0xffffffffu, vmax, 2));
                float s = 0.0f;
                #pragma unroll
                for (int j = 0; j < 16; j++) s += __expf(vals[j] - vmax);
                s += __shfl_xor_sync(0xffffffffu, s, 1);
                s += __shfl_xor_sync(0xffffffffu, s, 2);
                rqm[idx] = vmax; rqs[idx] = s; idx++;
            }
        }
        if (w < 4 && (lane & 3) == 0) {
            int id2 = 0;
            #pragma unroll
            for (int mi = 0; mi < 2; mi++)
                #pragma unroll
                for (int half = 0; half < 2; half++) {
                    sstat[wm + mi * 16 + half * 8 + gr] = make_float2(rqm[id2], rqs[id2]);
                    id2++;
                }
        }
        __syncthreads();
        if (w >= 4 && (lane & 3) == 0) {
            int id2 = 0;
            #pragma unroll
            for (int mi = 0; mi < 2; mi++)
                #pragma unroll
                for (int half = 0; half < 2; half++) {
                    int ml = wm + mi * 16 + half * 8 + gr;
                    float2 o = sstat[ml];
                    float M = fmaxf(o.x, rqm[id2]);
                    float S = o.y * __expf(o.x - M) + rqs[id2] * __expf(rqm[id2] - M);
                    stats[(size_t)(m0 + ml) * 80 + blockIdx.x] = make_float2(M, S);
                    id2++;
                }
        }
    } else {
        #pragma unroll
        for (int mi = 0; mi < 2; mi++) {
            #pragma unroll
            for (int half = 0; half < 2; half++) {
                int m = m0 + wm + mi * 16 + gr + half * 8;
                float2 rs = rowstat[m];
                #pragma unroll
                for (int nj = 0; nj < 8; nj++) {
                    int n = n0 + wn + nj * 8 + gc;
                    if (n < VV) {
                        float p0 = __expf(c[mi][nj][half * 2 + 0] - rs.x) * rs.y;
                        float p1 = __expf(c[mi][nj][half * 2 + 1] - rs.x) * rs.y;
                        *(float2*)(probs + (size_t)m * VV + n) = make_float2(p0, p1);
                    }
                }
            }
        }
    }
}

// combine the NTILE per-tile stats into (max, 1/sum) per row; one warp per row
__global__ void lm_reduce_kernel(const float2* __restrict__ stats,
                                 float2* __restrict__ rowstat) {
    int row = blockIdx.x * 8 + (threadIdx.x >> 5);
    int lane = threadIdx.x & 31;
    float M = -1e30f, S = 0.0f;
    for (int t = lane; t < NTILE; t += 32) {
        float2 v = stats[(size_t)row * 80 + t];
        float nm = fmaxf(M, v.x);
        S = S * __expf(M - nm) + v.y * __expf(v.x - nm);
        M = nm;
    }
    #pragma unroll
    for (int off = 16; off > 0; off >>= 1) {
        float m2 = __shfl_xor_sync(0xffffffffu, M, off);
        float s2 = __shfl_xor_sync(0xffffffffu, S, off);
        float nm = fmaxf(M, m2);
        S = S * __expf(M - nm) + s2 * __expf(m2 - nm);
        M = nm;
    }
    if (lane == 0) rowstat[row] = make_float2(M, 1.0f / S);
}

// ---------------- per-(edge,head) attention (QKV packed), writes bf16 hi/lo ---
__global__ void attn_kernel(const float* __restrict__ qkv,
                            bf* __restrict__ oh, bf* __restrict__ ol) {
    int b = blockIdx.x;
    int h = threadIdx.x >> 5;
    int lane = threadIdx.x & 31;
    int d0 = lane * 2;

    const size_t qbase = (size_t)b * LL * 768 + h * 64 + d0;
    float qr[LL][2], kr[LL][2], vr[LL][2];
    #pragma unroll
    for (int i = 0; i < LL; i++) {
        size_t ro = qbase + (size_t)i * 768;
        qr[i][0] = qkv[ro];           qr[i][1] = qkv[ro + 1];
        kr[i][0] = qkv[ro + 256];     kr[i][1] = qkv[ro + 257];
        vr[i][0] = qkv[ro + 512];     vr[i][1] = qkv[ro + 513];
    }

    float att[LL][LL];
    #pragma unroll
    for (int i = 0; i < LL; i++)
        #pragma unroll
        for (int j = 0; j < LL; j++) {
            float p = qr[i][0] * kr[j][0] + qr[i][1] * kr[j][1];
            #pragma unroll
            for (int off = 16; off > 0; off >>= 1)
                p += __shfl_xor_sync(0xffffffffu, p, off);
            att[i][j] = p * 0.125f;
        }

    #pragma unroll
    for (int i = 0; i < LL; i++) {
        float mx = att[i][0];
        #pragma unroll
        for (int j = 1; j < LL; j++) mx = fmaxf(mx, att[i][j]);
        float s = 0.0f;
        #pragma unroll
        for (int j = 0; j < LL; j++) { att[i][j] = expf(att[i][j] - mx); s += att[i][j]; }
        float inv = 1.0f / s;
        float o0 = 0.0f, o1 = 0.0f;
        #pragma unroll
        for (int j = 0; j < LL; j++) {
            float a = att[i][j] * inv;
            o0 = fmaf(a, vr[j][0], o0);
            o1 = fmaf(a, vr[j][1], o1);
        }
        size_t oi = (size_t)b * LL * DG + (size_t)i * DG + h * 64 + d0;
        float h0 = __bfloat162float(__float2bfloat16_rn(o0));
        float h1 = __bfloat162float(__float2bfloat16_rn(o1));
        *(uint32_t*)(oh + oi) = bf2pack(h0, h1);
        *(uint32_t*)(ol + oi) = bf2pack(o0 - h0, o1 - h1);
    }
}

// ---------------- host launch ----------------
#define SYM(var, sym) void* var##_v; cudaGetSymbolAddress(&var##_v, sym);

extern "C" void kernel_launch(void* const* d_in, const int* in_sizes, int n_in,
                              void* d_out, int out_size) {
    const int* node_tokens = (const int*)d_in[0];
    const int* edge_tokens = (const int*)d_in[1];
    const int* edge_index  = (const int*)d_in[2];
    const int* mask_rows   = (const int*)d_in[3];
    const float* emb    = (const float*)d_in[4];
    const float* W_msg  = (const float*)d_in[5];
    const float* W_node = (const float*)d_in[6];
    const float* lc1_w  = (const float*)d_in[7];
    const float* lc1_b  = (const float*)d_in[8];
    const float* lc2_w  = (const float*)d_in[9];
    const float* lc2_b  = (const float*)d_in[10];
    const float* Wq  = (const float*)d_in[11];
    const float* Wk  = (const float*)d_in[12];
    const float* Wv  = (const float*)d_in[13];
    const float* Wo  = (const float*)d_in[14];
    const float* Wf1 = (const float*)d_in[15];
    const float* Wf2 = (const float*)d_in[16];

    const int* src = edge_index;
    const int* dst = edge_index + NE;

    float* out = (float*)d_out;
    float* labels_ptr = nullptr;
    float* probs_ptr  = nullptr;
    long total = (long)NTOK * VV;
    if ((long)out_size >= total + NTOK) { labels_ptr = out; probs_ptr = out + NTOK; }
    else if ((long)out_size >= total)   { probs_ptr = out; }
    else                                { labels_ptr = out; }

    SYM(X, g_x)   SYM(MSG, g_msg) SYM(AGG, g_agg) SYM(H, g_h)
    SYM(Z, g_z)   SYM(QKV, g_qkv) SYM(X1, g_x1)
    SYM(STATS, g_stats) SYM(RSTAT, g_rowstat)
    SYM(Xh, g_Xh) SYM(Xl, g_Xl)   SYM(Eh, g_Eh)   SYM(El, g_El)
    SYM(Zh, g_Zh) SYM(Zl, g_Zl)   SYM(ATh, g_ATh) SYM(ATl, g_ATl)
    SYM(X1h, g_X1h) SYM(X1l, g_X1l) SYM(FFh, g_FFh) SYM(FFl, g_FFl)
    SYM(X2h, g_X2h) SYM(X2l, g_X2l) SYM(Yh, g_Yh)   SYM(Yl, g_Yl)
    SYM(embh, g_embh) SYM(embl, g_embl)
    SYM(WmsgTh, g_WmsgTh) SYM(WmsgTl, g_WmsgTl)
    SYM(WnodeTh, g_WnodeTh) SYM(WnodeTl, g_WnodeTl)
    SYM(lc1Th, g_lc1Th) SYM(lc1Tl, g_lc1Tl)
    SYM(qkvTh, g_qkvTh) SYM(qkvTl, g_qkvTl)
    SYM(WoTh, g_WoTh) SYM(WoTl, g_WoTl)
    SYM(Wf1Th, g_Wf1Th) SYM(Wf1Tl, g_Wf1Tl)
    SYM(Wf2Th, g_Wf2Th) SYM(Wf2Tl, g_Wf2Tl)
    SYM(lc2Th, g_lc2Th) SYM(lc2Tl, g_lc2Tl)

    cudaFuncSetAttribute(gemm_bf<0,3,1>, cudaFuncAttributeMaxDynamicSharedMemorySize, GSMEM);
    cudaFuncSetAttribute(gemm_bf<0,2,1>, cudaFuncAttributeMaxDynamicSharedMemorySize, GSMEM);
    cudaFuncSetAttribute(gemm_bf<1,1,3>, cudaFuncAttributeMaxDynamicSharedMemorySize, GSMEM);
    cudaFuncSetAttribute(gemm_bf<0,0,1>, cudaFuncAttributeMaxDynamicSharedMemorySize, GSMEM);
    cudaFuncSetAttribute(gemm_bf<0,4,3>, cudaFuncAttributeMaxDynamicSharedMemorySize, GSMEM);
    cudaFuncSetAttribute(gemm_bf<0,5,2>, cudaFuncAttributeMaxDynamicSharedMemorySize, GSMEM);
    cudaFuncSetAttribute(gemm_bf<0,4,2>, cudaFuncAttributeMaxDynamicSharedMemorySize, GSMEM);
    cudaFuncSetAttribute(gemm_bf<0,1,2>, cudaFuncAttributeMaxDynamicSharedMemorySize, GSMEM);
    cudaFuncSetAttribute(lm_gemm<0>, cudaFuncAttributeMaxDynamicSharedMemorySize, LMSMEM);
    cudaFuncSetAttribute(lm_gemm<1>, cudaFuncAttributeMaxDynamicSharedMemorySize, LMSMEM);

    // 0. all weight/emb splits in ONE kernel
    {
        SJobs jb;
        const float* srcs[NJOBS] = {W_msg, W_node, lc1_w, Wq, Wk, Wv, Wo, Wf1, Wf2, lc2_w, emb};
        bf* hs[NJOBS] = {(bf*)WmsgTh_v, (bf*)WnodeTh_v, (bf*)lc1Th_v,
                         (bf*)qkvTh_v, (bf*)qkvTh_v + DG*DG, (bf*)qkvTh_v + 2*DG*DG,
                         (bf*)WoTh_v, (bf*)Wf1Th_v, (bf*)Wf2Th_v, (bf*)lc2Th_v, (bf*)embh_v};
        bf* ls[NJOBS] = {(bf*)WmsgTl_v, (bf*)WnodeTl_v, (bf*)lc1Tl_v,
                         (bf*)qkvTl_v, (bf*)qkvTl_v + DG*DG, (bf*)qkvTl_v + 2*DG*DG,
                         (bf*)WoTl_v, (bf*)Wf1Tl_v, (bf*)Wf2Tl_v, (bf*)lc2Tl_v, (bf*)embl_v};
        int Ns[NJOBS] = {FD, FD, DG, DG, DG, DG, DG, 4*DG, DG, DD, 1};
        int Ks[NJOBS] = {FD, FD, DD, DG, DG, DG, DG, DG, 4*DG, DG, VV*DD};
        int cnt = 0;
        for (int j = 0; j < NJOBS; j++) {
            jb.src[j] = srcs[j]; jb.h[j] = hs[j]; jb.l[j] = ls[j];
            jb.N[j] = Ns[j]; jb.K[j] = Ks[j];
            cnt += Ks[j] * ((Ns[j] == 1) ? 1 : Ns[j]);
            jb.end[j] = cnt;
        }
        split_all_kernel<<<(cnt + 255) / 256, 256>>>(jb, cnt);
    }

    // 1. embeddings
    node_embed_kernel<<<(NN*FD+255)/256, 256>>>(node_tokens, emb, (float*)X_v, (bf*)Xh_v, (bf*)Xl_v);
    edge_mask_embed_kernel<<<NE, 256>>>(edge_tokens, mask_rows, emb, (bf*)Eh_v, (bf*)El_v, labels_ptr);

    if (probs_ptr == nullptr) return;

    zero_kernel<<<(NN*FD+255)/256, 256>>>((float*)AGG_v, NN*FD);
    // 2. msg = relu(e @ W_msg + x[src])
    gemm_bf<0,3,1><<<dim3(4,16), 256, GSMEM>>>((bf*)Eh_v, (bf*)El_v, (bf*)WmsgTh_v, (bf*)WmsgTl_v,
        (float*)MSG_v, nullptr, nullptr, NE, FD, FD, nullptr, (float*)X_v, src, nullptr, nullptr);
    // 3. agg = segment_sum(msg, dst)
    scatter_add_kernel<<<(NE*FD+255)/256, 256>>>((float*)MSG_v, dst, (float*)AGG_v);
    // 4. h = relu(x @ W_node + agg)
    gemm_bf<0,2,1><<<dim3(4,64), 256, GSMEM>>>((bf*)Xh_v, (bf*)Xl_v, (bf*)WnodeTh_v, (bf*)WnodeTl_v,
        (float*)H_v, nullptr, nullptr, NN, FD, FD, nullptr, (float*)AGG_v, nullptr, nullptr, nullptr);
    // 5. z = (h[src]+h[dst]) @ lc1_w + lc1_b
    gemm_bf<1,1,3><<<dim3(2,128), 256, GSMEM>>>(nullptr, nullptr, (bf*)lc1Th_v, (bf*)lc1Tl_v,
        (float*)Z_v, (bf*)Zh_v, (bf*)Zl_v, NTOK, DG, DD, lc1_b, nullptr, src, dst, (float*)H_v);
    // 6. qkv = z @ [Wq|Wk|Wv]
    gemm_bf<0,0,1><<<dim3(6,128), 256, GSMEM>>>((bf*)Zh_v, (bf*)Zl_v, (bf*)qkvTh_v, (bf*)qkvTl_v,
        (float*)QKV_v, nullptr, nullptr, NTOK, 3*DG, DG, nullptr, nullptr, nullptr, nullptr, nullptr);
    // 7. attention
    attn_kernel<<<NE, 128>>>((float*)QKV_v, (bf*)ATh_v, (bf*)ATl_v);
    // 8. x1 = z + attn @ Wo
    gemm_bf<0,4,3><<<dim3(2,128), 256, GSMEM>>>((bf*)ATh_v, (bf*)ATl_v, (bf*)WoTh_v, (bf*)WoTl_v,
        (float*)X1_v, (bf*)X1h_v, (bf*)X1l_v, NTOK, DG, DG, nullptr, (float*)Z_v, nullptr, nullptr, nullptr);
    // 9. ffn = gelu(x1 @ Wf1)
    gemm_bf<0,5,2><<<dim3(8,128), 256, GSMEM>>>((bf*)X1h_v, (bf*)X1l_v, (bf*)Wf1Th_v, (bf*)Wf1Tl_v,
        nullptr, (bf*)FFh_v, (bf*)FFl_v, NTOK, 4*DG, DG, nullptr, nullptr, nullptr, nullptr, nullptr);
    // 10. x2 = x1 + ffn @ Wf2
    gemm_bf<0,4,2><<<dim3(2,128), 256, GSMEM>>>((bf*)FFh_v, (bf*)FFl_v, (bf*)Wf2Th_v, (bf*)Wf2Tl_v,
        nullptr, (bf*)X2h_v, (bf*)X2l_v, NTOK, DG, 4*DG, nullptr, (float*)X1_v, nullptr, nullptr, nullptr);
    // 11. y = x2 @ lc2_w + lc2_b
    gemm_bf<0,1,2><<<dim3(1,128), 256, GSMEM>>>((bf*)X2h_v, (bf*)X2l_v, (bf*)lc2Th_v, (bf*)lc2Tl_v,
        nullptr, (bf*)Yh_v, (bf*)Yl_v, NTOK, DD, DG, lc2_b, nullptr, nullptr, nullptr, nullptr);
    // 12a. LM pass 1: per-tile softmax stats (no logits materialized)
    lm_gemm<0><<<dim3(NTILE,128), 256, LMSMEM>>>((bf*)Yh_v, (bf*)Yl_v, (bf*)embh_v, (bf*)embl_v,
        (float2*)STATS_v, nullptr, nullptr);
    // 12b. reduce stats per row
    lm_reduce_kernel<<<NTOK/8, 256>>>((float2*)STATS_v, (float2*)RSTAT_v);
    // 12c. LM pass 2: write probs directly
    lm_gemm<1><<<dim3(NTILE,128), 256, LMSMEM>>>((bf*)Yh_v, (bf*)Yl_v, (bf*)embh_v, (bf*)embl_v,
        nullptr, (float2*)RSTAT_v, probs_ptr);
}